// round 2
// baseline (speedup 1.0000x reference)
#include <cuda_runtime.h>
#include <math.h>

// ---------------------------------------------------------------------------
// RelationalPathGNN: 2-layer relational GNN with edge softmax.
// N=20000 nodes, E=160000 edges, EMB=64, HID=128, R=8 relations.
//
// Pipeline per launch (all recomputed -> deterministic, graph-capturable):
//   1. degrees + relation histogram (atomics)
//   2. tiny scan -> 64-aligned per-relation segment offsets
//   3. scatter edges into relation-grouped permutation
//   per layer:
//   4. fused gather + grouped GEMM  m[e] = [hn[src], ef[e], ne[dst]] @ W[eid[e]]
//   5. segment softmax over dst (max via ordered-uint atomicMax, sum via atomicAdd)
//   6. scatter-aggregate a*m into agg[dst] (float atomics)
//   7. epilogue: (agg + ne@L) * indeg^-1/2 + b, relu
// ---------------------------------------------------------------------------

namespace {
constexpr int N_   = 20000;
constexpr int E_   = 160000;
constexpr int EMB_ = 64;
constexpr int HID_ = 128;
constexpr int R_   = 8;
constexpr int TM   = 64;                       // edge-tile rows for grouped GEMM
constexpr int MTILES = (E_ + R_ * TM) / TM;    // 2508 worst-case tiles
}

// ------------------------- scratch (static device) -------------------------
__device__ float    g_m[(size_t)E_ * HID_];    // edge messages (reused L2: E*64)
__device__ float    g_h1[(size_t)N_ * HID_];   // layer-1 output
__device__ float    g_outdeg[N_];
__device__ float    g_indeg[N_];
__device__ float    g_inv_out[N_];
__device__ float    g_inv_in[N_];
__device__ int      g_cnt[R_];
__device__ int      g_off[R_ + 1];
__device__ int      g_cur[R_];
__device__ int      g_perm[E_ + R_ * TM];
__device__ float    g_zn[N_];
__device__ unsigned g_zmax[N_];
__device__ float    g_zbuf[E_];                // z, then reused as coef
__device__ float    g_ez[E_];
__device__ float    g_denom[N_];
__device__ float    g_agg[(size_t)N_ * HID_];

// ordered-uint encoding for float atomicMax (monotone over all finite floats)
__device__ __forceinline__ unsigned f2ord(float x) {
    unsigned u = __float_as_uint(x);
    return (u & 0x80000000u) ? ~u : (u | 0x80000000u);
}
__device__ __forceinline__ float ord2f(unsigned u) {
    return (u & 0x80000000u) ? __uint_as_float(u ^ 0x80000000u)
                             : __uint_as_float(~u);
}

// ------------------------------ prep kernels -------------------------------
__global__ void k_prep_zero() {
    int i = blockIdx.x * blockDim.x + threadIdx.x;
    if (i < N_) { g_outdeg[i] = 0.f; g_indeg[i] = 0.f; }
    if (i < R_) g_cnt[i] = 0;
}

__global__ void k_count(const int* __restrict__ src, const int* __restrict__ dst,
                        const int* __restrict__ eid) {
    int e = blockIdx.x * blockDim.x + threadIdx.x;
    if (e >= E_) return;
    atomicAdd(&g_outdeg[src[e]], 1.f);
    atomicAdd(&g_indeg[dst[e]], 1.f);
    atomicAdd(&g_cnt[eid[e]], 1);
}

__global__ void k_inv() {
    int i = blockIdx.x * blockDim.x + threadIdx.x;
    if (i >= N_) return;
    g_inv_out[i] = 1.f / sqrtf(fmaxf(g_outdeg[i], 1.f));
    g_inv_in[i]  = 1.f / sqrtf(fmaxf(g_indeg[i], 1.f));
}

__global__ void k_scan() {
    int o = 0;
    for (int r = 0; r < R_; r++) {
        g_off[r] = o;
        g_cur[r] = o;
        o += ((g_cnt[r] + TM - 1) / TM) * TM;   // 64-align each segment
    }
    g_off[R_] = o;
}

__global__ void k_scatter(const int* __restrict__ eid) {
    int e = blockIdx.x * blockDim.x + threadIdx.x;
    if (e >= E_) return;
    int pos = atomicAdd(&g_cur[eid[e]], 1);
    g_perm[pos] = e;
}

// --------------------------- per-layer zeroing -----------------------------
template <int NOUT>
__global__ void k_layer_zero() {
    int i = blockIdx.x * blockDim.x + threadIdx.x;
    if (i < N_ * NOUT) g_agg[i] = 0.f;
    if (i < N_) { g_zmax[i] = 0u; g_denom[i] = 0.f; }
}

// --------------------- fused gather + grouped GEMM -------------------------
// m[e, :] = concat(h[src[e]] * inv_out[src[e]], edge_feat[e], node_emb[dst[e]])
//           @ W[eid[e]]
// Rows are relation-grouped via g_perm; every 64-row tile is relation-uniform.
template <int FIN, int NOUT, bool H_FROM_H1>
__global__ void k_gemm(const float* __restrict__ hsrc_in,
                       const float* __restrict__ ef,
                       const float* __restrict__ ne,
                       const float* __restrict__ W,
                       const int* __restrict__ src,
                       const int* __restrict__ dst) {
    constexpr int K   = FIN + 2 * EMB_;
    constexpr int KT  = 16;
    constexpr int CPT = NOUT / 16;             // cols per thread (8 or 4)

    __shared__ float As[KT][TM + 4];
    __shared__ float Bs[KT][NOUT + 4];
    __shared__ int   s_e[TM];
    __shared__ int   s_src[TM];
    __shared__ int   s_dst[TM];
    __shared__ float s_sc[TM];

    const float* hsrc = H_FROM_H1 ? (const float*)g_h1 : hsrc_in;

    int tx = threadIdx.x, ty = threadIdx.y;
    int tid = ty * 16 + tx;
    int m0 = blockIdx.x * TM;
    if (m0 >= g_off[R_]) return;

    int rel = 0;
#pragma unroll
    for (int r = 1; r <= R_; r++)
        if (m0 >= g_off[r]) rel = r;
    int seg_end = g_off[rel] + g_cnt[rel];

    if (tid < TM) {
        int gi = m0 + tid;
        int e = (gi < seg_end) ? g_perm[gi] : -1;
        s_e[tid] = e;
        if (e >= 0) {
            int s = src[e];
            s_src[tid] = s;
            s_dst[tid] = dst[e];
            s_sc[tid]  = g_inv_out[s];
        }
    }
    __syncthreads();

    const float* Wr = W + (size_t)rel * K * NOUT;

    float acc[4][CPT];
#pragma unroll
    for (int i = 0; i < 4; i++)
#pragma unroll
        for (int j = 0; j < CPT; j++) acc[i][j] = 0.f;

    int am  = tid >> 2;           // row this thread gathers for A
    int ak0 = (tid & 3) * 4;      // first of 4 consecutive k's

    for (int kt = 0; kt < K / KT; kt++) {
        // ---- gather A tile (64 rows x 16 k's) ----
        {
            int kg = kt * KT + ak0;
            int e = s_e[am];
            float4 v = make_float4(0.f, 0.f, 0.f, 0.f);
            if (e >= 0) {
                if (kg < FIN) {
                    v = *(const float4*)(hsrc + (size_t)s_src[am] * FIN + kg);
                    float sc = s_sc[am];
                    v.x *= sc; v.y *= sc; v.z *= sc; v.w *= sc;
                } else if (kg < FIN + EMB_) {
                    v = *(const float4*)(ef + (size_t)e * EMB_ + (kg - FIN));
                } else {
                    v = *(const float4*)(ne + (size_t)s_dst[am] * EMB_ +
                                         (kg - FIN - EMB_));
                }
            }
            As[ak0 + 0][am] = v.x;
            As[ak0 + 1][am] = v.y;
            As[ak0 + 2][am] = v.z;
            As[ak0 + 3][am] = v.w;
        }
        // ---- load B tile (16 x NOUT) ----
#pragma unroll
        for (int c = 0; c < CPT / 4; c++) {
            int l   = (c * 256 + tid) * 4;
            int kk  = l / NOUT;
            int col = l % NOUT;
            float4 v = *(const float4*)(Wr + (size_t)(kt * KT + kk) * NOUT + col);
            *(float4*)&Bs[kk][col] = v;
        }
        __syncthreads();

#pragma unroll
        for (int kk = 0; kk < KT; kk++) {
            float4 a4 = *(const float4*)&As[kk][ty * 4];
            float av[4] = {a4.x, a4.y, a4.z, a4.w};
            float bv[CPT];
#pragma unroll
            for (int c = 0; c < CPT / 4; c++) {
                float4 b4 = *(const float4*)&Bs[kk][tx * CPT + c * 4];
                bv[c * 4 + 0] = b4.x;
                bv[c * 4 + 1] = b4.y;
                bv[c * 4 + 2] = b4.z;
                bv[c * 4 + 3] = b4.w;
            }
#pragma unroll
            for (int i = 0; i < 4; i++)
#pragma unroll
                for (int j = 0; j < CPT; j++)
                    acc[i][j] += av[i] * bv[j];
        }
        __syncthreads();
    }

    // ---- scatter-store m rows ----
#pragma unroll
    for (int i = 0; i < 4; i++) {
        int m = ty * 4 + i;
        int e = s_e[m];
        if (e >= 0) {
            float* dp = g_m + (size_t)e * NOUT + tx * CPT;
#pragma unroll
            for (int c = 0; c < CPT / 4; c++) {
                float4 v = make_float4(acc[i][c * 4 + 0], acc[i][c * 4 + 1],
                                       acc[i][c * 4 + 2], acc[i][c * 4 + 3]);
                *(float4*)(dp + c * 4) = v;
            }
        }
    }
}

// ----------------------------- attention path ------------------------------
// zn[n] = node_emb[n] . A[0:64]   (warp per node)
__global__ void k_zn(const float* __restrict__ ne, const float* __restrict__ A) {
    int gt = blockIdx.x * blockDim.x + threadIdx.x;
    int w = gt >> 5, lane = gt & 31;
    if (w >= N_) return;
    float s = ne[(size_t)w * 64 + lane] * A[lane] +
              ne[(size_t)w * 64 + 32 + lane] * A[32 + lane];
#pragma unroll
    for (int o = 16; o; o >>= 1) s += __shfl_xor_sync(0xffffffffu, s, o);
    if (lane == 0) g_zn[w] = s;
}

// z[e] = leaky_relu(zn[dst] + m[e] . A[EMB:]) ; atomicMax per-dst
template <int NOUT>
__global__ void k_logits(const float* __restrict__ At, const int* __restrict__ dst) {
    int gt = blockIdx.x * blockDim.x + threadIdx.x;
    int e = gt >> 5, lane = gt & 31;
    if (e >= E_) return;
    float s = 0.f;
#pragma unroll
    for (int c = 0; c < NOUT / 32; c++)
        s += g_m[(size_t)e * NOUT + c * 32 + lane] * At[c * 32 + lane];
#pragma unroll
    for (int o = 16; o; o >>= 1) s += __shfl_xor_sync(0xffffffffu, s, o);
    if (lane == 0) {
        int d = dst[e];
        float z = g_zn[d] + s;
        z = (z > 0.f) ? z : 0.01f * z;   // leaky_relu, slope 0.01
        g_zbuf[e] = z;
        atomicMax(&g_zmax[d], f2ord(z));
    }
}

__global__ void k_exp(const int* __restrict__ dst) {
    int e = blockIdx.x * blockDim.x + threadIdx.x;
    if (e >= E_) return;
    int d = dst[e];
    float ez = expf(g_zbuf[e] - ord2f(g_zmax[d]));
    g_ez[e] = ez;
    atomicAdd(&g_denom[d], ez);
}

__global__ void k_coef(const int* __restrict__ dst) {
    int e = blockIdx.x * blockDim.x + threadIdx.x;
    if (e >= E_) return;
    g_zbuf[e] = g_ez[e] / g_denom[dst[e]];
}

// agg[dst] += coef * m[e]   (one thread per (e, j))
template <int NOUT>
__global__ void k_agg(const int* __restrict__ dst) {
    int idx = blockIdx.x * blockDim.x + threadIdx.x;
    int e = idx / NOUT;
    int j = idx - e * NOUT;
    if (e >= E_) return;
    float v = g_zbuf[e] * g_m[idx];
    atomicAdd(&g_agg[(size_t)dst[e] * NOUT + j], v);
}

// out[n] = relu((agg[n] + ne[n] @ L) * inv_in[n] + b)
template <int NOUT, bool TO_H1>
__global__ void k_final(const float* __restrict__ ne, const float* __restrict__ L,
                        const float* __restrict__ b, float* __restrict__ out) {
    constexpr int Y = 256 / NOUT;   // nodes per compute pass
    __shared__ float sL[64 * NOUT];
    __shared__ float sne[Y][64];
    int tid = threadIdx.x;
    for (int i = tid; i < 64 * NOUT; i += 256) sL[i] = L[i];
    int n0 = blockIdx.x * 16;
    int ty = tid / NOUT, j = tid % NOUT;

    for (int it = 0; it < 16 / Y; it++) {
        __syncthreads();
        if (tid < Y * 64) {
            int nn = n0 + it * Y + tid / 64;
            sne[tid / 64][tid & 63] =
                (nn < N_) ? ne[(size_t)nn * 64 + (tid & 63)] : 0.f;
        }
        __syncthreads();
        int n = n0 + it * Y + ty;
        if (n < N_) {
            float acc = 0.f;
#pragma unroll
            for (int k = 0; k < 64; k++) acc += sne[ty][k] * sL[k * NOUT + j];
            float v = (g_agg[(size_t)n * NOUT + j] + acc) * g_inv_in[n] + b[j];
            v = fmaxf(v, 0.f);
            if (TO_H1) g_h1[(size_t)n * NOUT + j] = v;
            else       out[(size_t)n * NOUT + j] = v;
        }
    }
}

// ------------------------------- launcher ----------------------------------
extern "C" void kernel_launch(void* const* d_in, const int* in_sizes, int n_in,
                              void* d_out, int out_size) {
    const float* node_emb  = (const float*)d_in[0];
    const float* edge_feat = (const float*)d_in[1];
    const float* W1        = (const float*)d_in[2];
    const float* A1        = (const float*)d_in[3];
    const float* b1        = (const float*)d_in[4];
    const float* L1        = (const float*)d_in[5];
    const float* W2        = (const float*)d_in[6];
    const float* A2        = (const float*)d_in[7];
    const float* b2        = (const float*)d_in[8];
    const float* L2        = (const float*)d_in[9];
    const int*   eid       = (const int*)d_in[10];
    const int*   src       = (const int*)d_in[11];
    const int*   dst       = (const int*)d_in[12];
    float*       out       = (float*)d_out;
    (void)in_sizes; (void)n_in; (void)out_size;

    const int gN = (N_ + 255) / 256;
    const int gE = (E_ + 255) / 256;

    // prep (recomputed each launch: deterministic, capture-safe)
    k_prep_zero<<<gN, 256>>>();
    k_count<<<gE, 256>>>(src, dst, eid);
    k_inv<<<gN, 256>>>();
    k_scan<<<1, 1>>>();
    k_scatter<<<gE, 256>>>(eid);

    // ---- layer 1: FIN=64, K=192, NOUT=128 ----
    k_layer_zero<HID_><<<(N_ * HID_ + 255) / 256, 256>>>();
    k_gemm<EMB_, HID_, false><<<MTILES, dim3(16, 16)>>>(
        node_emb, edge_feat, node_emb, W1, src, dst);
    k_zn<<<(N_ + 3) / 4, 128>>>(node_emb, A1);
    k_logits<HID_><<<(E_ + 3) / 4, 128>>>(A1 + EMB_, dst);
    k_exp<<<gE, 256>>>(dst);
    k_coef<<<gE, 256>>>(dst);
    k_agg<HID_><<<(E_ * HID_) / 256, 256>>>(dst);
    k_final<HID_, true><<<(N_ + 15) / 16, 256>>>(node_emb, L1, b1, nullptr);

    // ---- layer 2: FIN=128, K=256, NOUT=64 ----
    k_layer_zero<EMB_><<<(N_ * EMB_ + 255) / 256, 256>>>();
    k_gemm<HID_, EMB_, true><<<MTILES, dim3(16, 16)>>>(
        nullptr, edge_feat, node_emb, W2, src, dst);
    k_zn<<<(N_ + 3) / 4, 128>>>(node_emb, A2);
    k_logits<EMB_><<<(E_ + 3) / 4, 128>>>(A2 + EMB_, dst);
    k_exp<<<gE, 256>>>(dst);
    k_coef<<<gE, 256>>>(dst);
    k_agg<EMB_><<<(E_ * EMB_) / 256, 256>>>(dst);
    k_final<EMB_, false><<<(N_ + 15) / 16, 256>>>(node_emb, L2, b2, out);
}

// round 3
// speedup vs baseline: 1.6751x; 1.6751x over previous
#include <cuda_runtime.h>
#include <math.h>
#include <stdint.h>

// ---------------------------------------------------------------------------
// RelationalPathGNN — round 3
//   * grouped gather-GEMM on tensor cores (mma.sync m16n8k8 tf32, rna-rounded)
//   * dst-CSR segment reduce replaces 30M-atomic aggregation
// ---------------------------------------------------------------------------

namespace {
constexpr int N_   = 20000;
constexpr int E_   = 160000;
constexpr int EMB_ = 64;
constexpr int HID_ = 128;
constexpr int R_   = 8;
constexpr int BM   = 128;                       // edge rows per GEMM tile
constexpr int MT   = E_ / BM + R_;              // 1258 worst-case tiles
constexpr int SCAN_BS = 512;
constexpr int SCAN_NB = (N_ + SCAN_BS - 1) / SCAN_BS;   // 40
}

// ------------------------- scratch (static device) -------------------------
__device__ float    g_m[(size_t)E_ * HID_];
__device__ float    g_h1[(size_t)N_ * HID_];
__device__ float    g_hn[(size_t)N_ * HID_];            // degree-scaled h
__device__ float    g_Wt1[R_ * (EMB_ + 2 * EMB_) * HID_];   // tf32-rounded W1
__device__ float    g_Wt2[R_ * (HID_ + 2 * EMB_) * EMB_];   // tf32-rounded W2
__device__ float    g_inv_out[N_], g_inv_in[N_];
__device__ int      g_outdeg_i[N_], g_indeg_i[N_];
__device__ int      g_cnt[R_], g_off[R_ + 1], g_cur[R_];
__device__ int      g_perm[E_ + R_ * BM];
__device__ int      g_doff[N_], g_dcur[N_], g_dtmp[N_], g_dblk[SCAN_NB];
__device__ int      g_eord[E_];
__device__ float    g_zn[N_];
__device__ unsigned g_zmax[N_];
__device__ float    g_zbuf[E_], g_ez[E_], g_denom[N_];
__device__ float    g_agg[(size_t)N_ * HID_];

// ordered-uint encoding for float atomicMax
__device__ __forceinline__ unsigned f2ord(float x) {
    unsigned u = __float_as_uint(x);
    return (u & 0x80000000u) ? ~u : (u | 0x80000000u);
}
__device__ __forceinline__ float ord2f(unsigned u) {
    return (u & 0x80000000u) ? __uint_as_float(u ^ 0x80000000u)
                             : __uint_as_float(~u);
}
__device__ __forceinline__ uint32_t tf32r(float x) {
    uint32_t u;
    asm("cvt.rna.tf32.f32 %0, %1;" : "=r"(u) : "f"(x));
    return u;
}

// ------------------------------ prep kernels -------------------------------
__global__ void k_prep_zero() {
    int i = blockIdx.x * blockDim.x + threadIdx.x;
    if (i < N_) { g_outdeg_i[i] = 0; g_indeg_i[i] = 0; }
    if (i < R_) g_cnt[i] = 0;
}

__global__ void k_count(const int* __restrict__ src, const int* __restrict__ dst,
                        const int* __restrict__ eid) {
    int e = blockIdx.x * blockDim.x + threadIdx.x;
    if (e >= E_) return;
    atomicAdd(&g_outdeg_i[src[e]], 1);
    atomicAdd(&g_indeg_i[dst[e]], 1);
    atomicAdd(&g_cnt[eid[e]], 1);
}

__global__ void k_inv() {
    int i = blockIdx.x * blockDim.x + threadIdx.x;
    if (i >= N_) return;
    g_inv_out[i] = 1.f / sqrtf(fmaxf((float)g_outdeg_i[i], 1.f));
    g_inv_in[i]  = 1.f / sqrtf(fmaxf((float)g_indeg_i[i], 1.f));
}

__global__ void k_scan() {
    int o = 0;
    for (int r = 0; r < R_; r++) {
        g_off[r] = o; g_cur[r] = o;
        o += ((g_cnt[r] + BM - 1) / BM) * BM;   // 128-align per relation
    }
    g_off[R_] = o;
}

__global__ void k_scatter(const int* __restrict__ eid) {
    int e = blockIdx.x * blockDim.x + threadIdx.x;
    if (e >= E_) return;
    int pos = atomicAdd(&g_cur[eid[e]], 1);
    g_perm[pos] = e;
}

// ---- dst CSR build (counting sort by dst) ----
__global__ void k_scan_blk() {
    __shared__ int sh[SCAN_BS];
    int i = blockIdx.x * SCAN_BS + threadIdx.x;
    int v = (i < N_) ? g_indeg_i[i] : 0;
    sh[threadIdx.x] = v;
    __syncthreads();
    for (int o = 1; o < SCAN_BS; o <<= 1) {
        int t = (threadIdx.x >= o) ? sh[threadIdx.x - o] : 0;
        __syncthreads();
        sh[threadIdx.x] += t;
        __syncthreads();
    }
    if (i < N_) g_dtmp[i] = sh[threadIdx.x] - v;
    if (threadIdx.x == SCAN_BS - 1) g_dblk[blockIdx.x] = sh[SCAN_BS - 1];
}

__global__ void k_scan_top() {
    if (threadIdx.x == 0) {
        int a = 0;
        for (int b = 0; b < SCAN_NB; b++) { int t = g_dblk[b]; g_dblk[b] = a; a += t; }
    }
}

__global__ void k_scan_add() {
    int i = blockIdx.x * blockDim.x + threadIdx.x;
    if (i >= N_) return;
    int o = g_dtmp[i] + g_dblk[i / SCAN_BS];
    g_doff[i] = o; g_dcur[i] = o;
}

__global__ void k_dscatter(const int* __restrict__ dst) {
    int e = blockIdx.x * blockDim.x + threadIdx.x;
    if (e >= E_) return;
    int p = atomicAdd(&g_dcur[dst[e]], 1);
    g_eord[p] = e;
}

// ---- weight tf32 rounding (layout preserved: [r][k][n]) ----
__global__ void k_wt(const float* __restrict__ W, float* __restrict__ out, int total) {
    int i = blockIdx.x * blockDim.x + threadIdx.x;
    if (i >= total) return;
    out[i] = __uint_as_float(tf32r(W[i]));
}

// hn = h * outdeg^-0.5
__global__ void k_hn(const float* __restrict__ h, int shift, int total) {
    int i = blockIdx.x * blockDim.x + threadIdx.x;
    if (i >= total) return;
    g_hn[i] = h[i] * g_inv_out[i >> shift];
}

__global__ void k_att_zero() {
    int i = blockIdx.x * blockDim.x + threadIdx.x;
    if (i < N_) { g_zmax[i] = 0u; g_denom[i] = 0.f; }
}

// --------------- tensor-core grouped gather-GEMM (tf32 mma) ----------------
// m[e,:] = concat(hn[src], ef[e], ne[dst]) @ W[eid[e]]
// Tile: 128 edge rows x NOUT cols, 8 warps (4 row-groups x 2 col-halves).
template <int FIN, int NOUT>
__global__ void __launch_bounds__(256)
k_gemm_mma(const float* __restrict__ ef, const float* __restrict__ ne,
           const float* __restrict__ Wt,
           const int* __restrict__ src, const int* __restrict__ dst) {
    constexpr int K   = FIN + 2 * EMB_;
    constexpr int NKC = K / 16;                 // 16-wide k-chunks
    constexpr int AST = 20;                     // As row stride (conflict-free)
    constexpr int BST = NOUT + 8;               // Bs row stride (conflict-free)
    constexpr int NF  = NOUT / 16;              // n-frags per warp (8 or 4)

    __shared__ float As[BM * AST];
    __shared__ float Bs[16 * BST];
    __shared__ const float* s_p[3][BM];
    __shared__ int s_e[BM];

    const int tid = threadIdx.x;
    const int m0  = blockIdx.x * BM;
    if (m0 >= g_off[R_]) return;

    int rel = 0;
#pragma unroll
    for (int r = 1; r < R_; r++)
        if (m0 >= g_off[r]) rel = r;
    const int seg_end = g_off[rel] + g_cnt[rel];

    if (tid < BM) {
        int gi = m0 + tid;
        int e = (gi < seg_end) ? g_perm[gi] : -1;
        s_e[tid] = e;
        if (e >= 0) {
            s_p[0][tid] = g_hn + (size_t)src[e] * FIN;
            s_p[1][tid] = ef + (size_t)e * EMB_;
            s_p[2][tid] = ne + (size_t)dst[e] * EMB_;
        } else {
            s_p[0][tid] = g_hn; s_p[1][tid] = g_hn; s_p[2][tid] = g_hn;
        }
    }
    __syncthreads();

    const float* Wr = Wt + (size_t)rel * K * NOUT;
    const int warp = tid >> 5, lane = tid & 31;
    const int wr = warp & 3, wc = warp >> 2;
    const int g = lane >> 2, q = lane & 3;

    float acc[2][NF][4];
#pragma unroll
    for (int mg = 0; mg < 2; mg++)
#pragma unroll
        for (int nf = 0; nf < NF; nf++)
#pragma unroll
            for (int j = 0; j < 4; j++) acc[mg][nf][j] = 0.f;

    for (int c = 0; c < NKC; c++) {
        const int k0 = c * 16;
        int seg, off;
        if (k0 < FIN)              { seg = 0; off = k0; }
        else if (k0 < FIN + EMB_)  { seg = 1; off = k0 - FIN; }
        else                       { seg = 2; off = k0 - FIN - EMB_; }

        // gather A chunk: 128 rows x 16 floats (tf32-rounded into smem)
#pragma unroll
        for (int t = 0; t < 2; t++) {
            int i   = tid + t * 256;
            int row = i >> 2;
            int q4  = (i & 3) * 4;
            float4 v = *(const float4*)(s_p[seg][row] + off + q4);
            uint4 u;
            u.x = tf32r(v.x); u.y = tf32r(v.y); u.z = tf32r(v.z); u.w = tf32r(v.w);
            *(uint4*)&As[row * AST + q4] = u;
        }
        // load B chunk: 16 x NOUT (pre-rounded weights)
        constexpr int NB4 = 16 * NOUT / 4;
#pragma unroll
        for (int t = 0; t < NB4 / 256; t++) {
            int i  = tid + t * 256;
            int kk = i / (NOUT / 4);
            int nn = (i % (NOUT / 4)) * 4;
            float4 v = *(const float4*)(Wr + (size_t)(k0 + kk) * NOUT + nn);
            *(float4*)&Bs[kk * BST + nn] = v;
        }
        __syncthreads();

#pragma unroll
        for (int ks = 0; ks < 2; ks++) {
            uint32_t a[2][4];
#pragma unroll
            for (int mg = 0; mg < 2; mg++) {
                const float* ap = As + (wr * 32 + mg * 16 + g) * AST + ks * 8 + q;
                a[mg][0] = __float_as_uint(ap[0]);
                a[mg][1] = __float_as_uint(ap[8 * AST]);
                a[mg][2] = __float_as_uint(ap[4]);
                a[mg][3] = __float_as_uint(ap[8 * AST + 4]);
            }
#pragma unroll
            for (int nf = 0; nf < NF; nf++) {
                const float* bp = Bs + (ks * 8 + q) * BST + wc * (NOUT / 2) + nf * 8 + g;
                uint32_t b0 = __float_as_uint(bp[0]);
                uint32_t b1 = __float_as_uint(bp[4 * BST]);
#pragma unroll
                for (int mg = 0; mg < 2; mg++) {
                    asm volatile(
                        "mma.sync.aligned.m16n8k8.row.col.f32.tf32.tf32.f32 "
                        "{%0,%1,%2,%3},{%4,%5,%6,%7},{%8,%9},{%0,%1,%2,%3};"
                        : "+f"(acc[mg][nf][0]), "+f"(acc[mg][nf][1]),
                          "+f"(acc[mg][nf][2]), "+f"(acc[mg][nf][3])
                        : "r"(a[mg][0]), "r"(a[mg][1]), "r"(a[mg][2]), "r"(a[mg][3]),
                          "r"(b0), "r"(b1));
                }
            }
        }
        __syncthreads();
    }

    // scatter-store accumulators (32B-sector-aligned per 4 lanes)
#pragma unroll
    for (int mg = 0; mg < 2; mg++) {
        int r0 = wr * 32 + mg * 16 + g;
        int e0 = s_e[r0], e1 = s_e[r0 + 8];
#pragma unroll
        for (int nf = 0; nf < NF; nf++) {
            int col = wc * (NOUT / 2) + nf * 8 + 2 * q;
            if (e0 >= 0)
                *(float2*)(g_m + (size_t)e0 * NOUT + col) =
                    make_float2(acc[mg][nf][0], acc[mg][nf][1]);
            if (e1 >= 0)
                *(float2*)(g_m + (size_t)e1 * NOUT + col) =
                    make_float2(acc[mg][nf][2], acc[mg][nf][3]);
        }
    }
}

// ----------------------------- attention path ------------------------------
__global__ void k_zn(const float* __restrict__ ne, const float* __restrict__ A) {
    int gt = blockIdx.x * blockDim.x + threadIdx.x;
    int w = gt >> 5, lane = gt & 31;
    if (w >= N_) return;
    float s = ne[(size_t)w * 64 + lane] * A[lane] +
              ne[(size_t)w * 64 + 32 + lane] * A[32 + lane];
#pragma unroll
    for (int o = 16; o; o >>= 1) s += __shfl_xor_sync(0xffffffffu, s, o);
    if (lane == 0) g_zn[w] = s;
}

template <int NOUT>
__global__ void k_logits(const float* __restrict__ At, const int* __restrict__ dst) {
    int gt = blockIdx.x * blockDim.x + threadIdx.x;
    int e = gt >> 5, lane = gt & 31;
    if (e >= E_) return;
    float s = 0.f;
#pragma unroll
    for (int c = 0; c < NOUT / 32; c++)
        s += g_m[(size_t)e * NOUT + c * 32 + lane] * At[c * 32 + lane];
#pragma unroll
    for (int o = 16; o; o >>= 1) s += __shfl_xor_sync(0xffffffffu, s, o);
    if (lane == 0) {
        int d = dst[e];
        float z = g_zn[d] + s;
        z = (z > 0.f) ? z : 0.01f * z;
        g_zbuf[e] = z;
        atomicMax(&g_zmax[d], f2ord(z));
    }
}

__global__ void k_exp(const int* __restrict__ dst) {
    int e = blockIdx.x * blockDim.x + threadIdx.x;
    if (e >= E_) return;
    int d = dst[e];
    float ez = expf(g_zbuf[e] - ord2f(g_zmax[d]));
    g_ez[e] = ez;
    atomicAdd(&g_denom[d], ez);
}

// warp-per-node CSR aggregation: agg[n] = sum_e (ez[e]/denom[n]) * m[e]
template <int NOUT>
__global__ void k_aggcsr() {
    int gw = (blockIdx.x * blockDim.x + threadIdx.x) >> 5;
    int lane = threadIdx.x & 31;
    if (gw >= N_) return;
    int beg = g_doff[gw], cnt = g_indeg_i[gw];
    if (NOUT == 128) {
        float4 acc = make_float4(0.f, 0.f, 0.f, 0.f);
        if (cnt > 0) {
            float inv = 1.f / g_denom[gw];
            for (int i = 0; i < cnt; i++) {
                int e = g_eord[beg + i];
                float cf = g_ez[e] * inv;
                float4 v = *(const float4*)(g_m + (size_t)e * 128 + lane * 4);
                acc.x += cf * v.x; acc.y += cf * v.y;
                acc.z += cf * v.z; acc.w += cf * v.w;
            }
        }
        *(float4*)(g_agg + (size_t)gw * 128 + lane * 4) = acc;
    } else {
        float2 acc = make_float2(0.f, 0.f);
        if (cnt > 0) {
            float inv = 1.f / g_denom[gw];
            for (int i = 0; i < cnt; i++) {
                int e = g_eord[beg + i];
                float cf = g_ez[e] * inv;
                float2 v = *(const float2*)(g_m + (size_t)e * 64 + lane * 2);
                acc.x += cf * v.x; acc.y += cf * v.y;
            }
        }
        *(float2*)(g_agg + (size_t)gw * 64 + lane * 2) = acc;
    }
}

// out[n] = relu((agg[n] + ne[n] @ L) * inv_in[n] + b)
template <int NOUT, bool TO_H1>
__global__ void k_final(const float* __restrict__ ne, const float* __restrict__ L,
                        const float* __restrict__ b, float* __restrict__ out) {
    constexpr int Y = 256 / NOUT;
    __shared__ float sL[64 * NOUT];
    __shared__ float sne[Y][64];
    int tid = threadIdx.x;
    for (int i = tid; i < 64 * NOUT; i += 256) sL[i] = L[i];
    int n0 = blockIdx.x * 16;
    int ty = tid / NOUT, j = tid % NOUT;

    for (int it = 0; it < 16 / Y; it++) {
        __syncthreads();
        if (tid < Y * 64) {
            int nn = n0 + it * Y + tid / 64;
            sne[tid / 64][tid & 63] =
                (nn < N_) ? ne[(size_t)nn * 64 + (tid & 63)] : 0.f;
        }
        __syncthreads();
        int n = n0 + it * Y + ty;
        if (n < N_) {
            float acc = 0.f;
#pragma unroll
            for (int k = 0; k < 64; k++) acc += sne[ty][k] * sL[k * NOUT + j];
            float v = (g_agg[(size_t)n * NOUT + j] + acc) * g_inv_in[n] + b[j];
            v = fmaxf(v, 0.f);
            if (TO_H1) g_h1[(size_t)n * NOUT + j] = v;
            else       out[(size_t)n * NOUT + j] = v;
        }
    }
}

// ------------------------------- launcher ----------------------------------
extern "C" void kernel_launch(void* const* d_in, const int* in_sizes, int n_in,
                              void* d_out, int out_size) {
    const float* node_emb  = (const float*)d_in[0];
    const float* edge_feat = (const float*)d_in[1];
    const float* W1        = (const float*)d_in[2];
    const float* A1        = (const float*)d_in[3];
    const float* b1        = (const float*)d_in[4];
    const float* L1        = (const float*)d_in[5];
    const float* W2        = (const float*)d_in[6];
    const float* A2        = (const float*)d_in[7];
    const float* b2        = (const float*)d_in[8];
    const float* L2        = (const float*)d_in[9];
    const int*   eid       = (const int*)d_in[10];
    const int*   src       = (const int*)d_in[11];
    const int*   dst       = (const int*)d_in[12];
    float*       out       = (float*)d_out;
    (void)in_sizes; (void)n_in; (void)out_size;

    const int gN = (N_ + 255) / 256;
    const int gE = (E_ + 255) / 256;

    float* d_Wt1; cudaGetSymbolAddress((void**)&d_Wt1, g_Wt1);
    float* d_Wt2; cudaGetSymbolAddress((void**)&d_Wt2, g_Wt2);
    float* d_h1;  cudaGetSymbolAddress((void**)&d_h1, g_h1);

    // ---- prep ----
    k_prep_zero<<<gN, 256>>>();
    k_count<<<gE, 256>>>(src, dst, eid);
    k_inv<<<gN, 256>>>();
    k_scan<<<1, 1>>>();
    k_scatter<<<gE, 256>>>(eid);
    k_scan_blk<<<SCAN_NB, SCAN_BS>>>();
    k_scan_top<<<1, 32>>>();
    k_scan_add<<<gN, 256>>>();
    k_dscatter<<<gE, 256>>>(dst);
    k_wt<<<(R_ * 192 * 128 + 255) / 256, 256>>>(W1, d_Wt1, R_ * 192 * 128);
    k_wt<<<(R_ * 256 * 64 + 255) / 256, 256>>>(W2, d_Wt2, R_ * 256 * 64);

    // ---- layer 1: FIN=64, K=192, NOUT=128 ----
    k_hn<<<(N_ * 64 + 255) / 256, 256>>>(node_emb, 6, N_ * 64);
    k_att_zero<<<gN, 256>>>();
    k_gemm_mma<64, 128><<<MT, 256>>>(edge_feat, node_emb, d_Wt1, src, dst);
    k_zn<<<(N_ + 3) / 4, 128>>>(node_emb, A1);
    k_logits<128><<<(E_ + 3) / 4, 128>>>(A1 + EMB_, dst);
    k_exp<<<gE, 256>>>(dst);
    k_aggcsr<128><<<(N_ * 32 + 255) / 256, 256>>>();
    k_final<128, true><<<(N_ + 15) / 16, 256>>>(node_emb, L1, b1, nullptr);

    // ---- layer 2: FIN=128, K=256, NOUT=64 ----
    k_hn<<<(N_ * 128 + 255) / 256, 256>>>(d_h1, 7, N_ * 128);
    k_att_zero<<<gN, 256>>>();
    k_gemm_mma<128, 64><<<MT, 256>>>(edge_feat, node_emb, d_Wt2, src, dst);
    k_zn<<<(N_ + 3) / 4, 128>>>(node_emb, A2);
    k_logits<64><<<(E_ + 3) / 4, 128>>>(A2 + EMB_, dst);
    k_exp<<<gE, 256>>>(dst);
    k_aggcsr<64><<<(N_ * 32 + 255) / 256, 256>>>();
    k_final<64, false><<<(N_ + 15) / 16, 256>>>(node_emb, L2, b2, out);
}

// round 5
// speedup vs baseline: 1.9669x; 1.1742x over previous
#include <cuda_runtime.h>
#include <math.h>
#include <stdint.h>

// ---------------------------------------------------------------------------
// RelationalPathGNN — round 5
//   * pipelined (cp.async double-buffered) tf32 mma.sync grouped gather-GEMM
//   * attention logits fused into GEMM epilogue
//   * softmax fused into dst-CSR segment reduce
// ---------------------------------------------------------------------------

namespace {
constexpr int N_   = 20000;
constexpr int E_   = 160000;
constexpr int EMB_ = 64;
constexpr int HID_ = 128;
constexpr int R_   = 8;
constexpr int BM   = 128;                       // edge rows per GEMM tile
constexpr int MT   = E_ / BM + R_;              // 1258 worst-case tiles
constexpr int SCAN_BS = 512;
constexpr int SCAN_NB = (N_ + SCAN_BS - 1) / SCAN_BS;   // 40
}

// ------------------------- scratch (static device) -------------------------
__device__ float    g_m[(size_t)E_ * HID_];
__device__ float    g_h1[(size_t)N_ * HID_];
__device__ float    g_hn[(size_t)N_ * HID_];            // degree-scaled, tf32-rounded
__device__ float    g_efr[(size_t)E_ * EMB_];           // tf32-rounded edge_feat
__device__ float    g_ner[(size_t)N_ * EMB_];           // tf32-rounded node_emb
__device__ float    g_Wt1[R_ * 192 * HID_];             // tf32-rounded W1
__device__ float    g_Wt2[R_ * 256 * EMB_];             // tf32-rounded W2
__device__ float    g_inv_out[N_], g_inv_in[N_];
__device__ int      g_outdeg_i[N_], g_indeg_i[N_];
__device__ int      g_cnt[R_], g_off[R_ + 1], g_cur[R_];
__device__ int      g_perm[E_ + R_ * BM];
__device__ int      g_doff[N_], g_dcur[N_], g_dtmp[N_], g_dblk[SCAN_NB];
__device__ int      g_eord[E_];
__device__ float    g_zn[N_];
__device__ float    g_zbuf[E_];
__device__ float    g_agg[(size_t)N_ * HID_];

// ------------------------------ helpers ------------------------------------
__device__ __forceinline__ uint32_t tf32r(float x) {
    uint32_t u;
    asm("cvt.rna.tf32.f32 %0, %1;" : "=r"(u) : "f"(x));
    return u;
}
__device__ __forceinline__ uint32_t smem_u32(const void* p) {
    uint32_t a;
    asm("{ .reg .u64 t; cvta.to.shared.u64 t, %1; cvt.u32.u64 %0, t; }"
        : "=r"(a) : "l"(p));
    return a;
}
__device__ __forceinline__ void cp_async16(uint32_t daddr, const void* gptr) {
    asm volatile("cp.async.cg.shared.global [%0], [%1], 16;"
                 :: "r"(daddr), "l"(gptr) : "memory");
}

// ------------------------------ prep kernels -------------------------------
__global__ void k_prep_zero() {
    int i = blockIdx.x * blockDim.x + threadIdx.x;
    if (i < N_) { g_outdeg_i[i] = 0; g_indeg_i[i] = 0; }
    if (i < R_) g_cnt[i] = 0;
}

__global__ void k_count(const int* __restrict__ src, const int* __restrict__ dst,
                        const int* __restrict__ eid) {
    int e = blockIdx.x * blockDim.x + threadIdx.x;
    if (e >= E_) return;
    atomicAdd(&g_outdeg_i[src[e]], 1);
    atomicAdd(&g_indeg_i[dst[e]], 1);
    atomicAdd(&g_cnt[eid[e]], 1);
}

__global__ void k_inv() {
    int i = blockIdx.x * blockDim.x + threadIdx.x;
    if (i >= N_) return;
    g_inv_out[i] = 1.f / sqrtf(fmaxf((float)g_outdeg_i[i], 1.f));
    g_inv_in[i]  = 1.f / sqrtf(fmaxf((float)g_indeg_i[i], 1.f));
}

__global__ void k_scan() {
    int o = 0;
    for (int r = 0; r < R_; r++) {
        g_off[r] = o; g_cur[r] = o;
        o += ((g_cnt[r] + BM - 1) / BM) * BM;
    }
    g_off[R_] = o;
}

__global__ void k_scatter(const int* __restrict__ eid) {
    int e = blockIdx.x * blockDim.x + threadIdx.x;
    if (e >= E_) return;
    int pos = atomicAdd(&g_cur[eid[e]], 1);
    g_perm[pos] = e;
}

// ---- dst CSR build ----
__global__ void k_scan_blk() {
    __shared__ int sh[SCAN_BS];
    int i = blockIdx.x * SCAN_BS + threadIdx.x;
    int v = (i < N_) ? g_indeg_i[i] : 0;
    sh[threadIdx.x] = v;
    __syncthreads();
    for (int o = 1; o < SCAN_BS; o <<= 1) {
        int t = (threadIdx.x >= o) ? sh[threadIdx.x - o] : 0;
        __syncthreads();
        sh[threadIdx.x] += t;
        __syncthreads();
    }
    if (i < N_) g_dtmp[i] = sh[threadIdx.x] - v;
    if (threadIdx.x == SCAN_BS - 1) g_dblk[blockIdx.x] = sh[SCAN_BS - 1];
}

__global__ void k_scan_top() {
    if (threadIdx.x == 0) {
        int a = 0;
        for (int b = 0; b < SCAN_NB; b++) { int t = g_dblk[b]; g_dblk[b] = a; a += t; }
    }
}

__global__ void k_scan_add() {
    int i = blockIdx.x * blockDim.x + threadIdx.x;
    if (i >= N_) return;
    int o = g_dtmp[i] + g_dblk[i / SCAN_BS];
    g_doff[i] = o; g_dcur[i] = o;
}

__global__ void k_dscatter(const int* __restrict__ dst) {
    int e = blockIdx.x * blockDim.x + threadIdx.x;
    if (e >= E_) return;
    int p = atomicAdd(&g_dcur[dst[e]], 1);
    g_eord[p] = e;
}

// elementwise tf32 rounding into a scratch copy
__global__ void k_round(const float* __restrict__ in, float* __restrict__ out,
                        int total) {
    int i = blockIdx.x * blockDim.x + threadIdx.x;
    if (i >= total) return;
    out[i] = __uint_as_float(tf32r(in[i]));
}

// hn = round_tf32(h * outdeg^-0.5)
__global__ void k_hn(const float* __restrict__ h, int shift, int total) {
    int i = blockIdx.x * blockDim.x + threadIdx.x;
    if (i >= total) return;
    g_hn[i] = __uint_as_float(tf32r(h[i] * g_inv_out[i >> shift]));
}

// zn[n] = node_emb[n] . A[0:64]
__global__ void k_zn(const float* __restrict__ ne, const float* __restrict__ A) {
    int gt = blockIdx.x * blockDim.x + threadIdx.x;
    int w = gt >> 5, lane = gt & 31;
    if (w >= N_) return;
    float s = ne[(size_t)w * 64 + lane] * A[lane] +
              ne[(size_t)w * 64 + 32 + lane] * A[32 + lane];
#pragma unroll
    for (int o = 16; o; o >>= 1) s += __shfl_xor_sync(0xffffffffu, s, o);
    if (lane == 0) g_zn[w] = s;
}

// --------- pipelined tf32 mma grouped gather-GEMM + fused logits -----------
// m[e,:] = concat(hn[src], ef[e], ne[dst]) @ W[eid[e]]
// z[e]   = leaky_relu(zn[dst[e]] + m[e] . At)
template <int FIN, int NOUT>
__global__ void __launch_bounds__(256)
k_gemm_mma(const float* __restrict__ Wt, const float* __restrict__ At,
           const int* __restrict__ src, const int* __restrict__ dst) {
    constexpr int K    = FIN + 2 * EMB_;
    constexpr int NC   = K / 32;               // 32-k chunks
    constexpr int AST  = 36;                   // As row stride (floats)
    constexpr int BST  = NOUT + 8;             // Bs row stride (floats)
    constexpr int AW   = BM * AST;             // floats per A buffer
    constexpr int BW   = 32 * BST;             // floats per B buffer
    constexpr int NF   = NOUT / 16;            // n-frags per warp

    extern __shared__ __align__(16) float dyn[];
    float* Asm = dyn;                          // 2 buffers
    float* Bsm = dyn + 2 * AW;                 // 2 buffers
    __shared__ const float* s_p[3][BM];
    __shared__ int   s_e[BM];
    __shared__ int   s_dst[BM];
    __shared__ float s_At[NOUT];
    __shared__ float s_zr[BM];

    const int tid = threadIdx.x;
    const int m0  = blockIdx.x * BM;
    if (m0 >= g_off[R_]) return;

    int rel = 0;
#pragma unroll
    for (int r = 1; r < R_; r++)
        if (m0 >= g_off[r]) rel = r;
    const int seg_end = g_off[rel] + g_cnt[rel];

    if (tid < BM) {
        int gi = m0 + tid;
        int e = (gi < seg_end) ? g_perm[gi] : -1;
        s_e[tid] = e;
        if (e >= 0) {
            s_p[0][tid] = g_hn + (size_t)src[e] * FIN;
            s_p[1][tid] = g_efr + (size_t)e * EMB_;
            s_p[2][tid] = g_ner + (size_t)dst[e] * EMB_;
            s_dst[tid]  = dst[e];
        } else {
            s_p[0][tid] = g_hn; s_p[1][tid] = g_hn; s_p[2][tid] = g_hn;
            s_dst[tid] = 0;
        }
    }
    if (tid < NOUT) s_At[tid] = At[tid];
    __syncthreads();

    const float* Wr = Wt + (size_t)rel * K * NOUT;
    const uint32_t a_s0 = smem_u32(Asm);
    const uint32_t b_s0 = smem_u32(Bsm);

    auto load_chunk = [&](int c, int buf) {
        const int k0 = c * 32;
        int seg, off;
        if (k0 < FIN)              { seg = 0; off = k0; }
        else if (k0 < FIN + EMB_)  { seg = 1; off = k0 - FIN; }
        else                       { seg = 2; off = k0 - FIN - EMB_; }
        const uint32_t ab = a_s0 + buf * AW * 4;
#pragma unroll
        for (int t = 0; t < 4; t++) {
            int i = tid + t * 256;
            int row = i >> 3, u = i & 7;
            cp_async16(ab + (row * AST) * 4 + u * 16, s_p[seg][row] + off + u * 4);
        }
        const float* wb = Wr + (size_t)k0 * NOUT;
        const uint32_t bb = b_s0 + buf * BW * 4;
#pragma unroll
        for (int t = 0; t < (32 * NOUT / 4) / 256; t++) {
            int i  = tid + t * 256;
            int kk = i / (NOUT / 4);
            int nn = (i % (NOUT / 4)) * 4;
            cp_async16(bb + (kk * BST + nn) * 4, wb + kk * NOUT + nn);
        }
        asm volatile("cp.async.commit_group;" ::: "memory");
    };

    const int warp = tid >> 5, lane = tid & 31;
    const int wr = warp & 3, wc = warp >> 2;
    const int g = lane >> 2, q = lane & 3;

    float acc[2][NF][4];
#pragma unroll
    for (int mg = 0; mg < 2; mg++)
#pragma unroll
        for (int nf = 0; nf < NF; nf++)
#pragma unroll
            for (int j = 0; j < 4; j++) acc[mg][nf][j] = 0.f;

    load_chunk(0, 0);

    for (int c = 0; c < NC; c++) {
        if (c + 1 < NC) {
            load_chunk(c + 1, (c + 1) & 1);
            asm volatile("cp.async.wait_group 1;" ::: "memory");
        } else {
            asm volatile("cp.async.wait_group 0;" ::: "memory");
        }
        __syncthreads();

        const float* ab = Asm + (c & 1) * AW;
        const float* bb = Bsm + (c & 1) * BW;
#pragma unroll
        for (int ks = 0; ks < 4; ks++) {
            uint32_t a[2][4];
#pragma unroll
            for (int mg = 0; mg < 2; mg++) {
                const float* ap = ab + (wr * 32 + mg * 16 + g) * AST + ks * 8 + q;
                a[mg][0] = __float_as_uint(ap[0]);
                a[mg][1] = __float_as_uint(ap[8 * AST]);
                a[mg][2] = __float_as_uint(ap[4]);
                a[mg][3] = __float_as_uint(ap[8 * AST + 4]);
            }
#pragma unroll
            for (int nf = 0; nf < NF; nf++) {
                const float* bp = bb + (ks * 8 + q) * BST + wc * (NOUT / 2) + nf * 8 + g;
                uint32_t b0 = __float_as_uint(bp[0]);
                uint32_t b1 = __float_as_uint(bp[4 * BST]);
#pragma unroll
                for (int mg = 0; mg < 2; mg++) {
                    asm volatile(
                        "mma.sync.aligned.m16n8k8.row.col.f32.tf32.tf32.f32 "
                        "{%0,%1,%2,%3},{%4,%5,%6,%7},{%8,%9},{%0,%1,%2,%3};"
                        : "+f"(acc[mg][nf][0]), "+f"(acc[mg][nf][1]),
                          "+f"(acc[mg][nf][2]), "+f"(acc[mg][nf][3])
                        : "r"(a[mg][0]), "r"(a[mg][1]), "r"(a[mg][2]), "r"(a[mg][3]),
                          "r"(b0), "r"(b1));
                }
            }
        }
        __syncthreads();
    }

    // ---- store m rows + fused attention-logit partials ----
    float p0[2], p1[2];
#pragma unroll
    for (int mg = 0; mg < 2; mg++) {
        int r0 = wr * 32 + mg * 16 + g;
        int e0 = s_e[r0], e1 = s_e[r0 + 8];
        p0[mg] = 0.f; p1[mg] = 0.f;
#pragma unroll
        for (int nf = 0; nf < NF; nf++) {
            int col = wc * (NOUT / 2) + nf * 8 + 2 * q;
            float a0 = s_At[col], a1 = s_At[col + 1];
            p0[mg] += acc[mg][nf][0] * a0 + acc[mg][nf][1] * a1;
            p1[mg] += acc[mg][nf][2] * a0 + acc[mg][nf][3] * a1;
            if (e0 >= 0)
                *(float2*)(g_m + (size_t)e0 * NOUT + col) =
                    make_float2(acc[mg][nf][0], acc[mg][nf][1]);
            if (e1 >= 0)
                *(float2*)(g_m + (size_t)e1 * NOUT + col) =
                    make_float2(acc[mg][nf][2], acc[mg][nf][3]);
        }
        // reduce across the 4 q-lanes (same row)
        p0[mg] += __shfl_xor_sync(0xffffffffu, p0[mg], 1);
        p0[mg] += __shfl_xor_sync(0xffffffffu, p0[mg], 2);
        p1[mg] += __shfl_xor_sync(0xffffffffu, p1[mg], 1);
        p1[mg] += __shfl_xor_sync(0xffffffffu, p1[mg], 2);
    }
    if (wc == 0 && q == 0) {
#pragma unroll
        for (int mg = 0; mg < 2; mg++) {
            s_zr[wr * 32 + mg * 16 + g]     = p0[mg];
            s_zr[wr * 32 + mg * 16 + g + 8] = p1[mg];
        }
    }
    __syncthreads();
    if (wc == 1 && q == 0) {
#pragma unroll
        for (int mg = 0; mg < 2; mg++) {
#pragma unroll
            for (int h = 0; h < 2; h++) {
                int r = wr * 32 + mg * 16 + g + h * 8;
                float tot = s_zr[r] + (h == 0 ? p0[mg] : p1[mg]);
                int e = s_e[r];
                if (e >= 0) {
                    float z = g_zn[s_dst[r]] + tot;
                    z = (z > 0.f) ? z : 0.01f * z;
                    g_zbuf[e] = z;
                }
            }
        }
    }
}

// ------------- fused segment softmax + CSR aggregation (warp/node) ---------
template <int NOUT>
__global__ void k_aggcsr() {
    int gw = (blockIdx.x * blockDim.x + threadIdx.x) >> 5;
    int lane = threadIdx.x & 31;
    if (gw >= N_) return;
    int beg = g_doff[gw], cnt = g_indeg_i[gw];

    float zm = -3.4e38f;
    for (int i = lane; i < cnt; i += 32)
        zm = fmaxf(zm, g_zbuf[g_eord[beg + i]]);
#pragma unroll
    for (int o = 16; o; o >>= 1)
        zm = fmaxf(zm, __shfl_xor_sync(0xffffffffu, zm, o));

    if (NOUT == 128) {
        float4 acc = make_float4(0.f, 0.f, 0.f, 0.f);
        float den = 0.f;
        for (int i = 0; i < cnt; i++) {
            int e = g_eord[beg + i];
            float w = expf(g_zbuf[e] - zm);
            den += w;
            float4 v = *(const float4*)(g_m + (size_t)e * 128 + lane * 4);
            acc.x += w * v.x; acc.y += w * v.y;
            acc.z += w * v.z; acc.w += w * v.w;
        }
        float inv = (cnt > 0) ? 1.f / den : 0.f;
        *(float4*)(g_agg + (size_t)gw * 128 + lane * 4) =
            make_float4(acc.x * inv, acc.y * inv, acc.z * inv, acc.w * inv);
    } else {
        float2 acc = make_float2(0.f, 0.f);
        float den = 0.f;
        for (int i = 0; i < cnt; i++) {
            int e = g_eord[beg + i];
            float w = expf(g_zbuf[e] - zm);
            den += w;
            float2 v = *(const float2*)(g_m + (size_t)e * 64 + lane * 2);
            acc.x += w * v.x; acc.y += w * v.y;
        }
        float inv = (cnt > 0) ? 1.f / den : 0.f;
        *(float2*)(g_agg + (size_t)gw * 64 + lane * 2) =
            make_float2(acc.x * inv, acc.y * inv);
    }
}

// out[n] = relu((agg[n] + ne[n] @ L) * inv_in[n] + b)
template <int NOUT, bool TO_H1>
__global__ void k_final(const float* __restrict__ ne, const float* __restrict__ L,
                        const float* __restrict__ b, float* __restrict__ out) {
    constexpr int Y = 256 / NOUT;
    __shared__ float sL[64 * NOUT];
    __shared__ float sne[Y][64];
    int tid = threadIdx.x;
    for (int i = tid; i < 64 * NOUT; i += 256) sL[i] = L[i];
    int n0 = blockIdx.x * 16;
    int ty = tid / NOUT, j = tid % NOUT;

    for (int it = 0; it < 16 / Y; it++) {
        __syncthreads();
        if (tid < Y * 64) {
            int nn = n0 + it * Y + tid / 64;
            sne[tid / 64][tid & 63] =
                (nn < N_) ? ne[(size_t)nn * 64 + (tid & 63)] : 0.f;
        }
        __syncthreads();
        int n = n0 + it * Y + ty;
        if (n < N_) {
            float acc = 0.f;
#pragma unroll
            for (int k = 0; k < 64; k++) acc += sne[ty][k] * sL[k * NOUT + j];
            float v = (g_agg[(size_t)n * NOUT + j] + acc) * g_inv_in[n] + b[j];
            v = fmaxf(v, 0.f);
            if (TO_H1) g_h1[(size_t)n * NOUT + j] = v;
            else       out[(size_t)n * NOUT + j] = v;
        }
    }
}

// ------------------------------- launcher ----------------------------------
extern "C" void kernel_launch(void* const* d_in, const int* in_sizes, int n_in,
                              void* d_out, int out_size) {
    const float* node_emb  = (const float*)d_in[0];
    const float* edge_feat = (const float*)d_in[1];
    const float* W1        = (const float*)d_in[2];
    const float* A1        = (const float*)d_in[3];
    const float* b1        = (const float*)d_in[4];
    const float* L1        = (const float*)d_in[5];
    const float* W2        = (const float*)d_in[6];
    const float* A2        = (const float*)d_in[7];
    const float* b2        = (const float*)d_in[8];
    const float* L2        = (const float*)d_in[9];
    const int*   eid       = (const int*)d_in[10];
    const int*   src       = (const int*)d_in[11];
    const int*   dst       = (const int*)d_in[12];
    float*       out       = (float*)d_out;
    (void)in_sizes; (void)n_in; (void)out_size;

    const int gN = (N_ + 255) / 256;
    const int gE = (E_ + 255) / 256;

    float* d_Wt1; cudaGetSymbolAddress((void**)&d_Wt1, g_Wt1);
    float* d_Wt2; cudaGetSymbolAddress((void**)&d_Wt2, g_Wt2);
    float* d_efr; cudaGetSymbolAddress((void**)&d_efr, g_efr);
    float* d_ner; cudaGetSymbolAddress((void**)&d_ner, g_ner);
    float* d_h1;  cudaGetSymbolAddress((void**)&d_h1, g_h1);

    // dynamic smem: 2 A buffers + 2 B buffers
    const int DS1 = (2 * BM * 36 + 2 * 32 * (HID_ + 8)) * 4;   // 71680
    const int DS2 = (2 * BM * 36 + 2 * 32 * (EMB_ + 8)) * 4;   // 55296
    cudaFuncSetAttribute(k_gemm_mma<64, 128>,
                         cudaFuncAttributeMaxDynamicSharedMemorySize, DS1);
    cudaFuncSetAttribute(k_gemm_mma<128, 64>,
                         cudaFuncAttributeMaxDynamicSharedMemorySize, DS2);

    // ---- prep ----
    k_prep_zero<<<gN, 256>>>();
    k_count<<<gE, 256>>>(src, dst, eid);
    k_inv<<<gN, 256>>>();
    k_scan<<<1, 1>>>();
    k_scatter<<<gE, 256>>>(eid);
    k_scan_blk<<<SCAN_NB, SCAN_BS>>>();
    k_scan_top<<<1, 32>>>();
    k_scan_add<<<gN, 256>>>();
    k_dscatter<<<gE, 256>>>(dst);
    k_round<<<(R_ * 192 * 128 + 255) / 256, 256>>>(W1, d_Wt1, R_ * 192 * 128);
    k_round<<<(R_ * 256 * 64 + 255) / 256, 256>>>(W2, d_Wt2, R_ * 256 * 64);
    k_round<<<(E_ * 64 + 255) / 256, 256>>>(edge_feat, d_efr, E_ * 64);
    k_round<<<(N_ * 64 + 255) / 256, 256>>>(node_emb, d_ner, N_ * 64);

    // ---- layer 1: FIN=64, K=192, NOUT=128 ----
    k_hn<<<(N_ * 64 + 255) / 256, 256>>>(node_emb, 6, N_ * 64);
    k_zn<<<(N_ + 3) / 4, 128>>>(node_emb, A1);
    k_gemm_mma<64, 128><<<MT, 256, DS1>>>(d_Wt1, A1 + EMB_, src, dst);
    k_aggcsr<128><<<(N_ * 32 + 255) / 256, 256>>>();
    k_final<128, true><<<(N_ + 15) / 16, 256>>>(node_emb, L1, b1, nullptr);

    // ---- layer 2: FIN=128, K=256, NOUT=64 ----
    k_hn<<<(N_ * 128 + 255) / 256, 256>>>(d_h1, 7, N_ * 128);
    k_zn<<<(N_ + 3) / 4, 128>>>(node_emb, A2);
    k_gemm_mma<128, 64><<<MT, 256, DS2>>>(d_Wt2, A2 + EMB_, src, dst);
    k_aggcsr<64><<<(N_ * 32 + 255) / 256, 256>>>();
    k_final<64, false><<<(N_ + 15) / 16, 256>>>(node_emb, L2, b2, out);
}

// round 6
// speedup vs baseline: 2.1961x; 1.1166x over previous
#include <cuda_runtime.h>
#include <math.h>
#include <stdint.h>

// ---------------------------------------------------------------------------
// RelationalPathGNN — round 6
//   * g_m stored in dst-CSR order -> streaming softmax-aggregation
//   * final epilogue (ne@L + norm + bias + relu) fused into aggregation
//   * launch-count reduction (13 kernels)
// ---------------------------------------------------------------------------

namespace {
constexpr int N_   = 20000;
constexpr int E_   = 160000;
constexpr int EMB_ = 64;
constexpr int HID_ = 128;
constexpr int R_   = 8;
constexpr int BM   = 128;                       // edge rows per GEMM tile
constexpr int MT   = E_ / BM + R_;              // 1258 worst-case tiles
constexpr int SCAN_BS = 512;
constexpr int SCAN_NB = (N_ + SCAN_BS - 1) / SCAN_BS;   // 40
constexpr int RW1 = R_ * 192 * HID_;            // 196608
constexpr int RW2 = R_ * 256 * EMB_;            // 131072
constexpr int REF = E_ * EMB_;                  // 10240000
constexpr int RNE = N_ * EMB_;                  // 1280000
}

// ------------------------- scratch (static device) -------------------------
__device__ float    g_m[(size_t)E_ * HID_];     // edge messages, dst-CSR order
__device__ float    g_z[E_];                    // logits, dst-CSR order
__device__ float    g_h1[(size_t)N_ * HID_];
__device__ float    g_hn[(size_t)N_ * HID_];    // degree-scaled, tf32-rounded
__device__ float    g_efr[(size_t)E_ * EMB_];   // tf32-rounded edge_feat
__device__ float    g_ner[(size_t)N_ * EMB_];   // tf32-rounded node_emb
__device__ float    g_Wt1[RW1];                 // tf32-rounded W1
__device__ float    g_Wt2[RW2];                 // tf32-rounded W2
__device__ float    g_inv_out[N_], g_inv_in[N_];
__device__ int      g_outdeg_i[N_], g_indeg_i[N_];
__device__ int      g_cnt[R_], g_off[R_ + 1], g_cur[R_];
__device__ int      g_perm[E_ + R_ * BM];
__device__ int      g_doff[N_], g_dcur[N_], g_dtmp[N_], g_dblk[SCAN_NB];
__device__ int      g_epos[E_];                 // edge -> dst-CSR position
__device__ float    g_zn1[N_], g_zn2[N_];

// ------------------------------ helpers ------------------------------------
__device__ __forceinline__ uint32_t tf32r(float x) {
    uint32_t u;
    asm("cvt.rna.tf32.f32 %0, %1;" : "=r"(u) : "f"(x));
    return u;
}
__device__ __forceinline__ uint32_t smem_u32(const void* p) {
    uint32_t a;
    asm("{ .reg .u64 t; cvta.to.shared.u64 t, %1; cvt.u32.u64 %0, t; }"
        : "=r"(a) : "l"(p));
    return a;
}
__device__ __forceinline__ void cp_async16(uint32_t daddr, const void* gptr) {
    asm volatile("cp.async.cg.shared.global [%0], [%1], 16;"
                 :: "r"(daddr), "l"(gptr) : "memory");
}

// ------------------------------ prep kernels -------------------------------
__global__ void k_prep_zero() {
    int i = blockIdx.x * blockDim.x + threadIdx.x;
    if (i < N_) { g_outdeg_i[i] = 0; g_indeg_i[i] = 0; }
    if (i < R_) g_cnt[i] = 0;
}

__global__ void k_count(const int* __restrict__ src, const int* __restrict__ dst,
                        const int* __restrict__ eid) {
    int e = blockIdx.x * blockDim.x + threadIdx.x;
    if (e >= E_) return;
    atomicAdd(&g_outdeg_i[src[e]], 1);
    atomicAdd(&g_indeg_i[dst[e]], 1);
    atomicAdd(&g_cnt[eid[e]], 1);
}

__global__ void k_scan() {
    int o = 0;
    for (int r = 0; r < R_; r++) {
        g_off[r] = o; g_cur[r] = o;
        o += ((g_cnt[r] + BM - 1) / BM) * BM;
    }
    g_off[R_] = o;
}

__global__ void k_scatter(const int* __restrict__ eid) {
    int e = blockIdx.x * blockDim.x + threadIdx.x;
    if (e >= E_) return;
    int pos = atomicAdd(&g_cur[eid[e]], 1);
    g_perm[pos] = e;
}

// ---- dst CSR build ----
__global__ void k_scan_blk() {
    __shared__ int sh[SCAN_BS];
    int i = blockIdx.x * SCAN_BS + threadIdx.x;
    int v = (i < N_) ? g_indeg_i[i] : 0;
    sh[threadIdx.x] = v;
    __syncthreads();
    for (int o = 1; o < SCAN_BS; o <<= 1) {
        int t = (threadIdx.x >= o) ? sh[threadIdx.x - o] : 0;
        __syncthreads();
        sh[threadIdx.x] += t;
        __syncthreads();
    }
    if (i < N_) g_dtmp[i] = sh[threadIdx.x] - v;
    if (threadIdx.x == SCAN_BS - 1) g_dblk[blockIdx.x] = sh[SCAN_BS - 1];
}

__global__ void k_scan_top() {
    if (threadIdx.x == 0) {
        int a = 0;
        for (int b = 0; b < SCAN_NB; b++) { int t = g_dblk[b]; g_dblk[b] = a; a += t; }
    }
}

// per-node: finish the scan AND compute the degree normalizers
__global__ void k_scan_add() {
    int i = blockIdx.x * blockDim.x + threadIdx.x;
    if (i >= N_) return;
    int o = g_dtmp[i] + g_dblk[i / SCAN_BS];
    g_doff[i] = o; g_dcur[i] = o;
    g_inv_out[i] = 1.f / sqrtf(fmaxf((float)g_outdeg_i[i], 1.f));
    g_inv_in[i]  = 1.f / sqrtf(fmaxf((float)g_indeg_i[i], 1.f));
}

__global__ void k_dscatter(const int* __restrict__ dst) {
    int e = blockIdx.x * blockDim.x + threadIdx.x;
    if (e >= E_) return;
    g_epos[e] = atomicAdd(&g_dcur[dst[e]], 1);
}

// one kernel rounds W1, W2, edge_feat, node_emb into their tf32 copies
__global__ void k_round_all(const float* __restrict__ W1, const float* __restrict__ W2,
                            const float* __restrict__ ef, const float* __restrict__ ne) {
    int i = blockIdx.x * blockDim.x + threadIdx.x;
    if (i < RW1) {
        g_Wt1[i] = __uint_as_float(tf32r(W1[i]));
    } else if (i < RW1 + RW2) {
        int j = i - RW1;
        g_Wt2[j] = __uint_as_float(tf32r(W2[j]));
    } else if (i < RW1 + RW2 + REF) {
        int j = i - RW1 - RW2;
        g_efr[j] = __uint_as_float(tf32r(ef[j]));
    } else if (i < RW1 + RW2 + REF + RNE) {
        int j = i - RW1 - RW2 - REF;
        g_ner[j] = __uint_as_float(tf32r(ne[j]));
    }
}

// hn = round_tf32(h * outdeg^-0.5)
__global__ void k_hn(const float* __restrict__ h, int shift, int total) {
    int i = blockIdx.x * blockDim.x + threadIdx.x;
    if (i >= total) return;
    g_hn[i] = __uint_as_float(tf32r(h[i] * g_inv_out[i >> shift]));
}

// zn1[n] = node_emb[n].A1[0:64], zn2[n] = node_emb[n].A2[0:64]
__global__ void k_zn(const float* __restrict__ ne, const float* __restrict__ A1,
                     const float* __restrict__ A2) {
    int gt = blockIdx.x * blockDim.x + threadIdx.x;
    int w = gt >> 5, lane = gt & 31;
    if (w >= N_) return;
    float x0 = ne[(size_t)w * 64 + lane], x1 = ne[(size_t)w * 64 + 32 + lane];
    float s1 = x0 * A1[lane] + x1 * A1[32 + lane];
    float s2 = x0 * A2[lane] + x1 * A2[32 + lane];
#pragma unroll
    for (int o = 16; o; o >>= 1) {
        s1 += __shfl_xor_sync(0xffffffffu, s1, o);
        s2 += __shfl_xor_sync(0xffffffffu, s2, o);
    }
    if (lane == 0) { g_zn1[w] = s1; g_zn2[w] = s2; }
}

// --------- pipelined tf32 mma grouped gather-GEMM + fused logits -----------
// m[p,:] = concat(hn[src], ef[e], ne[dst]) @ W[eid[e]],  p = g_epos[e]
// z[p]   = leaky_relu(zn[dst[e]] + m . At)
template <int FIN, int NOUT>
__global__ void __launch_bounds__(256)
k_gemm_mma(const float* __restrict__ Wt, const float* __restrict__ At,
           const float* __restrict__ zn,
           const int* __restrict__ src, const int* __restrict__ dst) {
    constexpr int K    = FIN + 2 * EMB_;
    constexpr int NC   = K / 32;               // 32-k chunks
    constexpr int AST  = 36;                   // As row stride (floats)
    constexpr int BST  = NOUT + 8;             // Bs row stride (floats)
    constexpr int AW   = BM * AST;
    constexpr int BW   = 32 * BST;
    constexpr int NF   = NOUT / 16;

    extern __shared__ __align__(16) float dyn[];
    float* Asm = dyn;
    float* Bsm = dyn + 2 * AW;
    __shared__ const float* s_p[3][BM];
    __shared__ int   s_pos[BM];
    __shared__ int   s_dst[BM];
    __shared__ float s_At[NOUT];
    __shared__ float s_zr[BM];

    const int tid = threadIdx.x;
    const int m0  = blockIdx.x * BM;
    if (m0 >= g_off[R_]) return;

    int rel = 0;
#pragma unroll
    for (int r = 1; r < R_; r++)
        if (m0 >= g_off[r]) rel = r;
    const int seg_end = g_off[rel] + g_cnt[rel];

    if (tid < BM) {
        int gi = m0 + tid;
        int e = (gi < seg_end) ? g_perm[gi] : -1;
        if (e >= 0) {
            s_pos[tid]  = g_epos[e];
            s_p[0][tid] = g_hn + (size_t)src[e] * FIN;
            s_p[1][tid] = g_efr + (size_t)e * EMB_;
            s_p[2][tid] = g_ner + (size_t)dst[e] * EMB_;
            s_dst[tid]  = dst[e];
        } else {
            s_pos[tid] = -1;
            s_p[0][tid] = g_hn; s_p[1][tid] = g_hn; s_p[2][tid] = g_hn;
            s_dst[tid] = 0;
        }
    }
    if (tid < NOUT) s_At[tid] = At[tid];
    __syncthreads();

    const float* Wr = Wt + (size_t)rel * K * NOUT;
    const uint32_t a_s0 = smem_u32(Asm);
    const uint32_t b_s0 = smem_u32(Bsm);

    auto load_chunk = [&](int c, int buf) {
        const int k0 = c * 32;
        int seg, off;
        if (k0 < FIN)              { seg = 0; off = k0; }
        else if (k0 < FIN + EMB_)  { seg = 1; off = k0 - FIN; }
        else                       { seg = 2; off = k0 - FIN - EMB_; }
        const uint32_t ab = a_s0 + buf * AW * 4;
#pragma unroll
        for (int t = 0; t < 4; t++) {
            int i = tid + t * 256;
            int row = i >> 3, u = i & 7;
            cp_async16(ab + (row * AST) * 4 + u * 16, s_p[seg][row] + off + u * 4);
        }
        const float* wb = Wr + (size_t)k0 * NOUT;
        const uint32_t bb = b_s0 + buf * BW * 4;
#pragma unroll
        for (int t = 0; t < (32 * NOUT / 4) / 256; t++) {
            int i  = tid + t * 256;
            int kk = i / (NOUT / 4);
            int nn = (i % (NOUT / 4)) * 4;
            cp_async16(bb + (kk * BST + nn) * 4, wb + kk * NOUT + nn);
        }
        asm volatile("cp.async.commit_group;" ::: "memory");
    };

    const int warp = tid >> 5, lane = tid & 31;
    const int wr = warp & 3, wc = warp >> 2;
    const int g = lane >> 2, q = lane & 3;

    float acc[2][NF][4];
#pragma unroll
    for (int mg = 0; mg < 2; mg++)
#pragma unroll
        for (int nf = 0; nf < NF; nf++)
#pragma unroll
            for (int j = 0; j < 4; j++) acc[mg][nf][j] = 0.f;

    load_chunk(0, 0);

    for (int c = 0; c < NC; c++) {
        if (c + 1 < NC) {
            load_chunk(c + 1, (c + 1) & 1);
            asm volatile("cp.async.wait_group 1;" ::: "memory");
        } else {
            asm volatile("cp.async.wait_group 0;" ::: "memory");
        }
        __syncthreads();

        const float* ab = Asm + (c & 1) * AW;
        const float* bb = Bsm + (c & 1) * BW;
#pragma unroll
        for (int ks = 0; ks < 4; ks++) {
            uint32_t a[2][4];
#pragma unroll
            for (int mg = 0; mg < 2; mg++) {
                const float* ap = ab + (wr * 32 + mg * 16 + g) * AST + ks * 8 + q;
                a[mg][0] = __float_as_uint(ap[0]);
                a[mg][1] = __float_as_uint(ap[8 * AST]);
                a[mg][2] = __float_as_uint(ap[4]);
                a[mg][3] = __float_as_uint(ap[8 * AST + 4]);
            }
#pragma unroll
            for (int nf = 0; nf < NF; nf++) {
                const float* bp = bb + (ks * 8 + q) * BST + wc * (NOUT / 2) + nf * 8 + g;
                uint32_t b0 = __float_as_uint(bp[0]);
                uint32_t b1 = __float_as_uint(bp[4 * BST]);
#pragma unroll
                for (int mg = 0; mg < 2; mg++) {
                    asm volatile(
                        "mma.sync.aligned.m16n8k8.row.col.f32.tf32.tf32.f32 "
                        "{%0,%1,%2,%3},{%4,%5,%6,%7},{%8,%9},{%0,%1,%2,%3};"
                        : "+f"(acc[mg][nf][0]), "+f"(acc[mg][nf][1]),
                          "+f"(acc[mg][nf][2]), "+f"(acc[mg][nf][3])
                        : "r"(a[mg][0]), "r"(a[mg][1]), "r"(a[mg][2]), "r"(a[mg][3]),
                          "r"(b0), "r"(b1));
                }
            }
        }
        __syncthreads();
    }

    // ---- store m rows (dst-CSR position) + fused attention-logit partials ----
    float p0[2], p1[2];
#pragma unroll
    for (int mg = 0; mg < 2; mg++) {
        int r0 = wr * 32 + mg * 16 + g;
        int d0 = s_pos[r0], d1 = s_pos[r0 + 8];
        p0[mg] = 0.f; p1[mg] = 0.f;
#pragma unroll
        for (int nf = 0; nf < NF; nf++) {
            int col = wc * (NOUT / 2) + nf * 8 + 2 * q;
            float a0 = s_At[col], a1 = s_At[col + 1];
            p0[mg] += acc[mg][nf][0] * a0 + acc[mg][nf][1] * a1;
            p1[mg] += acc[mg][nf][2] * a0 + acc[mg][nf][3] * a1;
            if (d0 >= 0)
                *(float2*)(g_m + (size_t)d0 * NOUT + col) =
                    make_float2(acc[mg][nf][0], acc[mg][nf][1]);
            if (d1 >= 0)
                *(float2*)(g_m + (size_t)d1 * NOUT + col) =
                    make_float2(acc[mg][nf][2], acc[mg][nf][3]);
        }
        p0[mg] += __shfl_xor_sync(0xffffffffu, p0[mg], 1);
        p0[mg] += __shfl_xor_sync(0xffffffffu, p0[mg], 2);
        p1[mg] += __shfl_xor_sync(0xffffffffu, p1[mg], 1);
        p1[mg] += __shfl_xor_sync(0xffffffffu, p1[mg], 2);
    }
    if (wc == 0 && q == 0) {
#pragma unroll
        for (int mg = 0; mg < 2; mg++) {
            s_zr[wr * 32 + mg * 16 + g]     = p0[mg];
            s_zr[wr * 32 + mg * 16 + g + 8] = p1[mg];
        }
    }
    __syncthreads();
    if (wc == 1 && q == 0) {
#pragma unroll
        for (int mg = 0; mg < 2; mg++) {
#pragma unroll
            for (int h = 0; h < 2; h++) {
                int r = wr * 32 + mg * 16 + g + h * 8;
                int p = s_pos[r];
                if (p >= 0) {
                    float tot = s_zr[r] + (h == 0 ? p0[mg] : p1[mg]);
                    float z = zn[s_dst[r]] + tot;
                    z = (z > 0.f) ? z : 0.01f * z;
                    g_z[p] = z;
                }
            }
        }
    }
}

// ------ fused: segment softmax + streaming aggregation + final epilogue ----
// out[n] = relu((softmax_agg(n) + ne[n]@L) * inv_in[n] + b)
// warp-per-node; m rows and z are CONTIGUOUS per node (dst-CSR order).
template <int NOUT, bool TO_H1>
__global__ void __launch_bounds__(256)
k_aggfinal(const float* __restrict__ ne, const float* __restrict__ L,
           const float* __restrict__ b, float* __restrict__ out) {
    __shared__ float sL[64 * NOUT];
    const int tid = threadIdx.x;
    for (int i = tid; i < 64 * NOUT; i += 256) sL[i] = L[i];
    __syncthreads();

    const int warp = tid >> 5, lane = tid & 31;
#pragma unroll
    for (int it = 0; it < 4; it++) {
        int n = blockIdx.x * 32 + it * 8 + warp;
        if (n >= N_) continue;
        int beg = g_doff[n], cnt = g_indeg_i[n];

        float zm = -3.4e38f;
        for (int i = lane; i < cnt; i += 32) zm = fmaxf(zm, g_z[beg + i]);
#pragma unroll
        for (int o = 16; o; o >>= 1)
            zm = fmaxf(zm, __shfl_xor_sync(0xffffffffu, zm, o));

        float iv = g_inv_in[n];
        const float* nr = ne + (size_t)n * 64;

        if (NOUT == 128) {
            float4 acc = make_float4(0.f, 0.f, 0.f, 0.f);
            float den = 0.f;
            const float* mrow = g_m + (size_t)beg * 128 + lane * 4;
            for (int i = 0; i < cnt; i++) {
                float w = expf(g_z[beg + i] - zm);
                den += w;
                float4 v = *(const float4*)(mrow + (size_t)i * 128);
                acc.x += w * v.x; acc.y += w * v.y;
                acc.z += w * v.z; acc.w += w * v.w;
            }
            float invw = (cnt > 0) ? 1.f / den : 0.f;
            float4 lt = make_float4(0.f, 0.f, 0.f, 0.f);
#pragma unroll 4
            for (int k = 0; k < 64; k++) {
                float a = nr[k];
                float4 lv = *(const float4*)(sL + k * 128 + lane * 4);
                lt.x += a * lv.x; lt.y += a * lv.y;
                lt.z += a * lv.z; lt.w += a * lv.w;
            }
            float4 bb = *(const float4*)(b + lane * 4);
            float4 r;
            r.x = fmaxf((acc.x * invw + lt.x) * iv + bb.x, 0.f);
            r.y = fmaxf((acc.y * invw + lt.y) * iv + bb.y, 0.f);
            r.z = fmaxf((acc.z * invw + lt.z) * iv + bb.z, 0.f);
            r.w = fmaxf((acc.w * invw + lt.w) * iv + bb.w, 0.f);
            *(float4*)((TO_H1 ? g_h1 : out) + (size_t)n * 128 + lane * 4) = r;
        } else {
            float2 acc = make_float2(0.f, 0.f);
            float den = 0.f;
            const float* mrow = g_m + (size_t)beg * 64 + lane * 2;
            for (int i = 0; i < cnt; i++) {
                float w = expf(g_z[beg + i] - zm);
                den += w;
                float2 v = *(const float2*)(mrow + (size_t)i * 64);
                acc.x += w * v.x; acc.y += w * v.y;
            }
            float invw = (cnt > 0) ? 1.f / den : 0.f;
            float2 lt = make_float2(0.f, 0.f);
#pragma unroll 4
            for (int k = 0; k < 64; k++) {
                float a = nr[k];
                float2 lv = *(const float2*)(sL + k * 64 + lane * 2);
                lt.x += a * lv.x; lt.y += a * lv.y;
            }
            float2 bb = *(const float2*)(b + lane * 2);
            float2 r;
            r.x = fmaxf((acc.x * invw + lt.x) * iv + bb.x, 0.f);
            r.y = fmaxf((acc.y * invw + lt.y) * iv + bb.y, 0.f);
            *(float2*)((TO_H1 ? g_h1 : out) + (size_t)n * 64 + lane * 2) = r;
        }
    }
}

// ------------------------------- launcher ----------------------------------
extern "C" void kernel_launch(void* const* d_in, const int* in_sizes, int n_in,
                              void* d_out, int out_size) {
    const float* node_emb  = (const float*)d_in[0];
    const float* edge_feat = (const float*)d_in[1];
    const float* W1        = (const float*)d_in[2];
    const float* A1        = (const float*)d_in[3];
    const float* b1        = (const float*)d_in[4];
    const float* L1        = (const float*)d_in[5];
    const float* W2        = (const float*)d_in[6];
    const float* A2        = (const float*)d_in[7];
    const float* b2        = (const float*)d_in[8];
    const float* L2        = (const float*)d_in[9];
    const int*   eid       = (const int*)d_in[10];
    const int*   src       = (const int*)d_in[11];
    const int*   dst       = (const int*)d_in[12];
    float*       out       = (float*)d_out;
    (void)in_sizes; (void)n_in; (void)out_size;

    const int gN = (N_ + 255) / 256;
    const int gE = (E_ + 255) / 256;

    float* d_Wt1; cudaGetSymbolAddress((void**)&d_Wt1, g_Wt1);
    float* d_Wt2; cudaGetSymbolAddress((void**)&d_Wt2, g_Wt2);
    float* d_zn1; cudaGetSymbolAddress((void**)&d_zn1, g_zn1);
    float* d_zn2; cudaGetSymbolAddress((void**)&d_zn2, g_zn2);
    float* d_h1;  cudaGetSymbolAddress((void**)&d_h1, g_h1);

    const int DS1 = (2 * BM * 36 + 2 * 32 * (HID_ + 8)) * 4;   // 71680
    const int DS2 = (2 * BM * 36 + 2 * 32 * (EMB_ + 8)) * 4;   // 55296
    cudaFuncSetAttribute(k_gemm_mma<64, 128>,
                         cudaFuncAttributeMaxDynamicSharedMemorySize, DS1);
    cudaFuncSetAttribute(k_gemm_mma<128, 64>,
                         cudaFuncAttributeMaxDynamicSharedMemorySize, DS2);

    // ---- prep ----
    k_prep_zero<<<gN, 256>>>();
    k_count<<<gE, 256>>>(src, dst, eid);
    k_scan<<<1, 1>>>();
    k_scatter<<<gE, 256>>>(eid);
    k_scan_blk<<<SCAN_NB, SCAN_BS>>>();
    k_scan_top<<<1, 32>>>();
    k_scan_add<<<gN, 256>>>();
    k_dscatter<<<gE, 256>>>(dst);
    k_round_all<<<(RW1 + RW2 + REF + RNE + 255) / 256, 256>>>(
        W1, W2, edge_feat, node_emb);
    k_zn<<<(N_ + 3) / 4, 128>>>(node_emb, A1, A2);

    // ---- layer 1: FIN=64, K=192, NOUT=128 ----
    k_hn<<<(N_ * 64 + 255) / 256, 256>>>(node_emb, 6, N_ * 64);
    k_gemm_mma<64, 128><<<MT, 256, DS1>>>(d_Wt1, A1 + EMB_, d_zn1, src, dst);
    k_aggfinal<128, true><<<(N_ + 31) / 32, 256>>>(node_emb, L1, b1, nullptr);

    // ---- layer 2: FIN=128, K=256, NOUT=64 ----
    k_hn<<<(N_ * 128 + 255) / 256, 256>>>(d_h1, 7, N_ * 128);
    k_gemm_mma<128, 64><<<MT, 256, DS2>>>(d_Wt2, A2 + EMB_, d_zn2, src, dst);
    k_aggfinal<64, false><<<(N_ + 31) / 32, 256>>>(node_emb, L2, b2, out);
}

// round 7
// speedup vs baseline: 2.5940x; 1.1812x over previous
#include <cuda_runtime.h>
#include <math.h>
#include <stdint.h>

// ---------------------------------------------------------------------------
// RelationalPathGNN — round 7
//   * block-aggregated histogram atomics (k_count / k_scatter)
//   * hn computation folded into k_round_all (L1) and k_aggfinal (L2)
//   * GEMM __launch_bounds__(256,2)
// ---------------------------------------------------------------------------

namespace {
constexpr int N_   = 20000;
constexpr int E_   = 160000;
constexpr int EMB_ = 64;
constexpr int HID_ = 128;
constexpr int R_   = 8;
constexpr int BM   = 128;                       // edge rows per GEMM tile
constexpr int MT   = E_ / BM + R_;              // 1258 worst-case tiles
constexpr int SCAN_BS = 512;
constexpr int SCAN_NB = (N_ + SCAN_BS - 1) / SCAN_BS;   // 40
constexpr int RW1 = R_ * 192 * HID_;            // 196608
constexpr int RW2 = R_ * 256 * EMB_;            // 131072
constexpr int REF = E_ * EMB_;                  // 10240000
constexpr int RNE = N_ * EMB_;                  // 1280000
constexpr int RTOT = RW1 + RW2 + REF + RNE + RNE;   // + layer-1 hn
}

// ------------------------- scratch (static device) -------------------------
__device__ float    g_m[(size_t)E_ * HID_];     // edge messages, dst-CSR order
__device__ float    g_z[E_];                    // logits, dst-CSR order
__device__ float    g_hn[(size_t)N_ * HID_];    // degree-scaled, tf32-rounded
__device__ float    g_efr[(size_t)E_ * EMB_];   // tf32-rounded edge_feat
__device__ float    g_ner[(size_t)N_ * EMB_];   // tf32-rounded node_emb
__device__ float    g_Wt1[RW1];                 // tf32-rounded W1
__device__ float    g_Wt2[RW2];                 // tf32-rounded W2
__device__ float    g_inv_out[N_], g_inv_in[N_];
__device__ int      g_outdeg_i[N_], g_indeg_i[N_];
__device__ int      g_cnt[R_], g_off[R_ + 1], g_cur[R_];
__device__ int      g_perm[E_ + R_ * BM];
__device__ int      g_doff[N_], g_dcur[N_], g_dtmp[N_], g_dblk[SCAN_NB];
__device__ int      g_epos[E_];                 // edge -> dst-CSR position
__device__ float    g_zn1[N_], g_zn2[N_];

// ------------------------------ helpers ------------------------------------
__device__ __forceinline__ uint32_t tf32r(float x) {
    uint32_t u;
    asm("cvt.rna.tf32.f32 %0, %1;" : "=r"(u) : "f"(x));
    return u;
}
__device__ __forceinline__ uint32_t smem_u32(const void* p) {
    uint32_t a;
    asm("{ .reg .u64 t; cvta.to.shared.u64 t, %1; cvt.u32.u64 %0, t; }"
        : "=r"(a) : "l"(p));
    return a;
}
__device__ __forceinline__ void cp_async16(uint32_t daddr, const void* gptr) {
    asm volatile("cp.async.cg.shared.global [%0], [%1], 16;"
                 :: "r"(daddr), "l"(gptr) : "memory");
}

// ------------------------------ prep kernels -------------------------------
__global__ void k_prep_zero() {
    int i = blockIdx.x * blockDim.x + threadIdx.x;
    if (i < N_) { g_outdeg_i[i] = 0; g_indeg_i[i] = 0; }
    if (i < R_) g_cnt[i] = 0;
}

// degrees (spread atomics) + block-aggregated relation histogram
__global__ void k_count(const int* __restrict__ src, const int* __restrict__ dst,
                        const int* __restrict__ eid) {
    __shared__ int h[R_];
    int tid = threadIdx.x;
    if (tid < R_) h[tid] = 0;
    __syncthreads();
    int e = blockIdx.x * blockDim.x + tid;
    if (e < E_) {
        atomicAdd(&g_outdeg_i[src[e]], 1);
        atomicAdd(&g_indeg_i[dst[e]], 1);
        atomicAdd(&h[eid[e]], 1);
    }
    __syncthreads();
    if (tid < R_ && h[tid] > 0) atomicAdd(&g_cnt[tid], h[tid]);
}

__global__ void k_scan() {
    int o = 0;
    for (int r = 0; r < R_; r++) {
        g_off[r] = o; g_cur[r] = o;
        o += ((g_cnt[r] + BM - 1) / BM) * BM;
    }
    g_off[R_] = o;
}

// block-aggregated scatter: one global atomic per (block, relation)
__global__ void k_scatter(const int* __restrict__ eid) {
    __shared__ int h[R_], base[R_], cur[R_];
    int tid = threadIdx.x;
    if (tid < R_) { h[tid] = 0; cur[tid] = 0; }
    __syncthreads();
    int e = blockIdx.x * blockDim.x + tid;
    int r = (e < E_) ? eid[e] : -1;
    if (r >= 0) atomicAdd(&h[r], 1);
    __syncthreads();
    if (tid < R_ && h[tid] > 0) base[tid] = atomicAdd(&g_cur[tid], h[tid]);
    __syncthreads();
    if (r >= 0) {
        int p = base[r] + atomicAdd(&cur[r], 1);
        g_perm[p] = e;
    }
}

// ---- dst CSR build ----
__global__ void k_scan_blk() {
    __shared__ int sh[SCAN_BS];
    int i = blockIdx.x * SCAN_BS + threadIdx.x;
    int v = (i < N_) ? g_indeg_i[i] : 0;
    sh[threadIdx.x] = v;
    __syncthreads();
    for (int o = 1; o < SCAN_BS; o <<= 1) {
        int t = (threadIdx.x >= o) ? sh[threadIdx.x - o] : 0;
        __syncthreads();
        sh[threadIdx.x] += t;
        __syncthreads();
    }
    if (i < N_) g_dtmp[i] = sh[threadIdx.x] - v;
    if (threadIdx.x == SCAN_BS - 1) g_dblk[blockIdx.x] = sh[SCAN_BS - 1];
}

__global__ void k_scan_top() {
    if (threadIdx.x == 0) {
        int a = 0;
        for (int b = 0; b < SCAN_NB; b++) { int t = g_dblk[b]; g_dblk[b] = a; a += t; }
    }
}

__global__ void k_scan_add() {
    int i = blockIdx.x * blockDim.x + threadIdx.x;
    if (i >= N_) return;
    int o = g_dtmp[i] + g_dblk[i / SCAN_BS];
    g_doff[i] = o; g_dcur[i] = o;
    g_inv_out[i] = 1.f / sqrtf(fmaxf((float)g_outdeg_i[i], 1.f));
    g_inv_in[i]  = 1.f / sqrtf(fmaxf((float)g_indeg_i[i], 1.f));
}

__global__ void k_dscatter(const int* __restrict__ dst) {
    int e = blockIdx.x * blockDim.x + threadIdx.x;
    if (e >= E_) return;
    g_epos[e] = atomicAdd(&g_dcur[dst[e]], 1);
}

// rounds W1, W2, edge_feat, node_emb; also builds layer-1 hn
__global__ void k_round_all(const float* __restrict__ W1, const float* __restrict__ W2,
                            const float* __restrict__ ef, const float* __restrict__ ne) {
    int i = blockIdx.x * blockDim.x + threadIdx.x;
    if (i < RW1) {
        g_Wt1[i] = __uint_as_float(tf32r(W1[i]));
    } else if (i < RW1 + RW2) {
        int j = i - RW1;
        g_Wt2[j] = __uint_as_float(tf32r(W2[j]));
    } else if (i < RW1 + RW2 + REF) {
        int j = i - RW1 - RW2;
        g_efr[j] = __uint_as_float(tf32r(ef[j]));
    } else if (i < RW1 + RW2 + REF + RNE) {
        int j = i - RW1 - RW2 - REF;
        g_ner[j] = __uint_as_float(tf32r(ne[j]));
    } else if (i < RTOT) {
        int j = i - RW1 - RW2 - REF - RNE;
        g_hn[j] = __uint_as_float(tf32r(ne[j] * g_inv_out[j >> 6]));
    }
}

// zn1[n] = node_emb[n].A1[0:64], zn2[n] = node_emb[n].A2[0:64]
__global__ void k_zn(const float* __restrict__ ne, const float* __restrict__ A1,
                     const float* __restrict__ A2) {
    int gt = blockIdx.x * blockDim.x + threadIdx.x;
    int w = gt >> 5, lane = gt & 31;
    if (w >= N_) return;
    float x0 = ne[(size_t)w * 64 + lane], x1 = ne[(size_t)w * 64 + 32 + lane];
    float s1 = x0 * A1[lane] + x1 * A1[32 + lane];
    float s2 = x0 * A2[lane] + x1 * A2[32 + lane];
#pragma unroll
    for (int o = 16; o; o >>= 1) {
        s1 += __shfl_xor_sync(0xffffffffu, s1, o);
        s2 += __shfl_xor_sync(0xffffffffu, s2, o);
    }
    if (lane == 0) { g_zn1[w] = s1; g_zn2[w] = s2; }
}

// --------- pipelined tf32 mma grouped gather-GEMM + fused logits -----------
template <int FIN, int NOUT>
__global__ void __launch_bounds__(256, 2)
k_gemm_mma(const float* __restrict__ Wt, const float* __restrict__ At,
           const float* __restrict__ zn,
           const int* __restrict__ src, const int* __restrict__ dst) {
    constexpr int K    = FIN + 2 * EMB_;
    constexpr int NC   = K / 32;
    constexpr int AST  = 36;
    constexpr int BST  = NOUT + 8;
    constexpr int AW   = BM * AST;
    constexpr int BW   = 32 * BST;
    constexpr int NF   = NOUT / 16;

    extern __shared__ __align__(16) float dyn[];
    float* Asm = dyn;
    float* Bsm = dyn + 2 * AW;
    __shared__ const float* s_p[3][BM];
    __shared__ int   s_pos[BM];
    __shared__ int   s_dst[BM];
    __shared__ float s_At[NOUT];
    __shared__ float s_zr[BM];

    const int tid = threadIdx.x;
    const int m0  = blockIdx.x * BM;
    if (m0 >= g_off[R_]) return;

    int rel = 0;
#pragma unroll
    for (int r = 1; r < R_; r++)
        if (m0 >= g_off[r]) rel = r;
    const int seg_end = g_off[rel] + g_cnt[rel];

    if (tid < BM) {
        int gi = m0 + tid;
        int e = (gi < seg_end) ? g_perm[gi] : -1;
        if (e >= 0) {
            s_pos[tid]  = g_epos[e];
            s_p[0][tid] = g_hn + (size_t)src[e] * FIN;
            s_p[1][tid] = g_efr + (size_t)e * EMB_;
            s_p[2][tid] = g_ner + (size_t)dst[e] * EMB_;
            s_dst[tid]  = dst[e];
        } else {
            s_pos[tid] = -1;
            s_p[0][tid] = g_hn; s_p[1][tid] = g_hn; s_p[2][tid] = g_hn;
            s_dst[tid] = 0;
        }
    }
    if (tid < NOUT) s_At[tid] = At[tid];
    __syncthreads();

    const float* Wr = Wt + (size_t)rel * K * NOUT;
    const uint32_t a_s0 = smem_u32(Asm);
    const uint32_t b_s0 = smem_u32(Bsm);

    auto load_chunk = [&](int c, int buf) {
        const int k0 = c * 32;
        int seg, off;
        if (k0 < FIN)              { seg = 0; off = k0; }
        else if (k0 < FIN + EMB_)  { seg = 1; off = k0 - FIN; }
        else                       { seg = 2; off = k0 - FIN - EMB_; }
        const uint32_t ab = a_s0 + buf * AW * 4;
#pragma unroll
        for (int t = 0; t < 4; t++) {
            int i = tid + t * 256;
            int row = i >> 3, u = i & 7;
            cp_async16(ab + (row * AST) * 4 + u * 16, s_p[seg][row] + off + u * 4);
        }
        const float* wb = Wr + (size_t)k0 * NOUT;
        const uint32_t bb = b_s0 + buf * BW * 4;
#pragma unroll
        for (int t = 0; t < (32 * NOUT / 4) / 256; t++) {
            int i  = tid + t * 256;
            int kk = i / (NOUT / 4);
            int nn = (i % (NOUT / 4)) * 4;
            cp_async16(bb + (kk * BST + nn) * 4, wb + kk * NOUT + nn);
        }
        asm volatile("cp.async.commit_group;" ::: "memory");
    };

    const int warp = tid >> 5, lane = tid & 31;
    const int wr = warp & 3, wc = warp >> 2;
    const int g = lane >> 2, q = lane & 3;

    float acc[2][NF][4];
#pragma unroll
    for (int mg = 0; mg < 2; mg++)
#pragma unroll
        for (int nf = 0; nf < NF; nf++)
#pragma unroll
            for (int j = 0; j < 4; j++) acc[mg][nf][j] = 0.f;

    load_chunk(0, 0);

    for (int c = 0; c < NC; c++) {
        if (c + 1 < NC) {
            load_chunk(c + 1, (c + 1) & 1);
            asm volatile("cp.async.wait_group 1;" ::: "memory");
        } else {
            asm volatile("cp.async.wait_group 0;" ::: "memory");
        }
        __syncthreads();

        const float* ab = Asm + (c & 1) * AW;
        const float* bb = Bsm + (c & 1) * BW;
#pragma unroll
        for (int ks = 0; ks < 4; ks++) {
            uint32_t a[2][4];
#pragma unroll
            for (int mg = 0; mg < 2; mg++) {
                const float* ap = ab + (wr * 32 + mg * 16 + g) * AST + ks * 8 + q;
                a[mg][0] = __float_as_uint(ap[0]);
                a[mg][1] = __float_as_uint(ap[8 * AST]);
                a[mg][2] = __float_as_uint(ap[4]);
                a[mg][3] = __float_as_uint(ap[8 * AST + 4]);
            }
#pragma unroll
            for (int nf = 0; nf < NF; nf++) {
                const float* bp = bb + (ks * 8 + q) * BST + wc * (NOUT / 2) + nf * 8 + g;
                uint32_t b0 = __float_as_uint(bp[0]);
                uint32_t b1 = __float_as_uint(bp[4 * BST]);
#pragma unroll
                for (int mg = 0; mg < 2; mg++) {
                    asm volatile(
                        "mma.sync.aligned.m16n8k8.row.col.f32.tf32.tf32.f32 "
                        "{%0,%1,%2,%3},{%4,%5,%6,%7},{%8,%9},{%0,%1,%2,%3};"
                        : "+f"(acc[mg][nf][0]), "+f"(acc[mg][nf][1]),
                          "+f"(acc[mg][nf][2]), "+f"(acc[mg][nf][3])
                        : "r"(a[mg][0]), "r"(a[mg][1]), "r"(a[mg][2]), "r"(a[mg][3]),
                          "r"(b0), "r"(b1));
                }
            }
        }
        __syncthreads();
    }

    // ---- store m rows (dst-CSR) + fused attention-logit partials ----
    float p0[2], p1[2];
#pragma unroll
    for (int mg = 0; mg < 2; mg++) {
        int r0 = wr * 32 + mg * 16 + g;
        int d0 = s_pos[r0], d1 = s_pos[r0 + 8];
        p0[mg] = 0.f; p1[mg] = 0.f;
#pragma unroll
        for (int nf = 0; nf < NF; nf++) {
            int col = wc * (NOUT / 2) + nf * 8 + 2 * q;
            float a0 = s_At[col], a1 = s_At[col + 1];
            p0[mg] += acc[mg][nf][0] * a0 + acc[mg][nf][1] * a1;
            p1[mg] += acc[mg][nf][2] * a0 + acc[mg][nf][3] * a1;
            if (d0 >= 0)
                *(float2*)(g_m + (size_t)d0 * NOUT + col) =
                    make_float2(acc[mg][nf][0], acc[mg][nf][1]);
            if (d1 >= 0)
                *(float2*)(g_m + (size_t)d1 * NOUT + col) =
                    make_float2(acc[mg][nf][2], acc[mg][nf][3]);
        }
        p0[mg] += __shfl_xor_sync(0xffffffffu, p0[mg], 1);
        p0[mg] += __shfl_xor_sync(0xffffffffu, p0[mg], 2);
        p1[mg] += __shfl_xor_sync(0xffffffffu, p1[mg], 1);
        p1[mg] += __shfl_xor_sync(0xffffffffu, p1[mg], 2);
    }
    if (wc == 0 && q == 0) {
#pragma unroll
        for (int mg = 0; mg < 2; mg++) {
            s_zr[wr * 32 + mg * 16 + g]     = p0[mg];
            s_zr[wr * 32 + mg * 16 + g + 8] = p1[mg];
        }
    }
    __syncthreads();
    if (wc == 1 && q == 0) {
#pragma unroll
        for (int mg = 0; mg < 2; mg++) {
#pragma unroll
            for (int h = 0; h < 2; h++) {
                int r = wr * 32 + mg * 16 + g + h * 8;
                int p = s_pos[r];
                if (p >= 0) {
                    float tot = s_zr[r] + (h == 0 ? p0[mg] : p1[mg]);
                    float z = zn[s_dst[r]] + tot;
                    z = (z > 0.f) ? z : 0.01f * z;
                    g_z[p] = z;
                }
            }
        }
    }
}

// ------ fused: segment softmax + streaming aggregation + final epilogue ----
// OUT_HN: layer 1 — write g_hn = tf32r(relu(...) * inv_out[n]) for layer 2.
template <int NOUT, bool OUT_HN>
__global__ void __launch_bounds__(256)
k_aggfinal(const float* __restrict__ ne, const float* __restrict__ L,
           const float* __restrict__ b, float* __restrict__ out) {
    __shared__ float sL[64 * NOUT];
    const int tid = threadIdx.x;
    for (int i = tid; i < 64 * NOUT; i += 256) sL[i] = L[i];
    __syncthreads();

    const int warp = tid >> 5, lane = tid & 31;
#pragma unroll
    for (int it = 0; it < 4; it++) {
        int n = blockIdx.x * 32 + it * 8 + warp;
        if (n >= N_) continue;
        int beg = g_doff[n], cnt = g_indeg_i[n];

        float zm = -3.4e38f;
        for (int i = lane; i < cnt; i += 32) zm = fmaxf(zm, g_z[beg + i]);
#pragma unroll
        for (int o = 16; o; o >>= 1)
            zm = fmaxf(zm, __shfl_xor_sync(0xffffffffu, zm, o));

        float iv = g_inv_in[n];
        const float* nr = ne + (size_t)n * 64;

        if (NOUT == 128) {
            float4 acc = make_float4(0.f, 0.f, 0.f, 0.f);
            float den = 0.f;
            const float* mrow = g_m + (size_t)beg * 128 + lane * 4;
            for (int i = 0; i < cnt; i++) {
                float w = expf(g_z[beg + i] - zm);
                den += w;
                float4 v = *(const float4*)(mrow + (size_t)i * 128);
                acc.x += w * v.x; acc.y += w * v.y;
                acc.z += w * v.z; acc.w += w * v.w;
            }
            float invw = (cnt > 0) ? 1.f / den : 0.f;
            float4 lt = make_float4(0.f, 0.f, 0.f, 0.f);
#pragma unroll 4
            for (int k = 0; k < 64; k++) {
                float a = nr[k];
                float4 lv = *(const float4*)(sL + k * 128 + lane * 4);
                lt.x += a * lv.x; lt.y += a * lv.y;
                lt.z += a * lv.z; lt.w += a * lv.w;
            }
            float4 bb = *(const float4*)(b + lane * 4);
            float4 r;
            r.x = fmaxf((acc.x * invw + lt.x) * iv + bb.x, 0.f);
            r.y = fmaxf((acc.y * invw + lt.y) * iv + bb.y, 0.f);
            r.z = fmaxf((acc.z * invw + lt.z) * iv + bb.z, 0.f);
            r.w = fmaxf((acc.w * invw + lt.w) * iv + bb.w, 0.f);
            if (OUT_HN) {
                float so = g_inv_out[n];
                float4 hv;
                hv.x = __uint_as_float(tf32r(r.x * so));
                hv.y = __uint_as_float(tf32r(r.y * so));
                hv.z = __uint_as_float(tf32r(r.z * so));
                hv.w = __uint_as_float(tf32r(r.w * so));
                *(float4*)(g_hn + (size_t)n * 128 + lane * 4) = hv;
            } else {
                *(float4*)(out + (size_t)n * 128 + lane * 4) = r;
            }
        } else {
            float2 acc = make_float2(0.f, 0.f);
            float den = 0.f;
            const float* mrow = g_m + (size_t)beg * 64 + lane * 2;
            for (int i = 0; i < cnt; i++) {
                float w = expf(g_z[beg + i] - zm);
                den += w;
                float2 v = *(const float2*)(mrow + (size_t)i * 64);
                acc.x += w * v.x; acc.y += w * v.y;
            }
            float invw = (cnt > 0) ? 1.f / den : 0.f;
            float2 lt = make_float2(0.f, 0.f);
#pragma unroll 4
            for (int k = 0; k < 64; k++) {
                float a = nr[k];
                float2 lv = *(const float2*)(sL + k * 64 + lane * 2);
                lt.x += a * lv.x; lt.y += a * lv.y;
            }
            float2 bb = *(const float2*)(b + lane * 2);
            float2 r;
            r.x = fmaxf((acc.x * invw + lt.x) * iv + bb.x, 0.f);
            r.y = fmaxf((acc.y * invw + lt.y) * iv + bb.y, 0.f);
            *(float2*)(out + (size_t)n * 64 + lane * 2) = r;
        }
    }
}

// ------------------------------- launcher ----------------------------------
extern "C" void kernel_launch(void* const* d_in, const int* in_sizes, int n_in,
                              void* d_out, int out_size) {
    const float* node_emb  = (const float*)d_in[0];
    const float* edge_feat = (const float*)d_in[1];
    const float* W1        = (const float*)d_in[2];
    const float* A1        = (const float*)d_in[3];
    const float* b1        = (const float*)d_in[4];
    const float* L1        = (const float*)d_in[5];
    const float* W2        = (const float*)d_in[6];
    const float* A2        = (const float*)d_in[7];
    const float* b2        = (const float*)d_in[8];
    const float* L2        = (const float*)d_in[9];
    const int*   eid       = (const int*)d_in[10];
    const int*   src       = (const int*)d_in[11];
    const int*   dst       = (const int*)d_in[12];
    float*       out       = (float*)d_out;
    (void)in_sizes; (void)n_in; (void)out_size;

    const int gN = (N_ + 255) / 256;
    const int gE = (E_ + 255) / 256;

    float* d_Wt1; cudaGetSymbolAddress((void**)&d_Wt1, g_Wt1);
    float* d_Wt2; cudaGetSymbolAddress((void**)&d_Wt2, g_Wt2);
    float* d_zn1; cudaGetSymbolAddress((void**)&d_zn1, g_zn1);
    float* d_zn2; cudaGetSymbolAddress((void**)&d_zn2, g_zn2);

    const int DS1 = (2 * BM * 36 + 2 * 32 * (HID_ + 8)) * 4;   // 71680
    const int DS2 = (2 * BM * 36 + 2 * 32 * (EMB_ + 8)) * 4;   // 55296
    cudaFuncSetAttribute(k_gemm_mma<64, 128>,
                         cudaFuncAttributeMaxDynamicSharedMemorySize, DS1);
    cudaFuncSetAttribute(k_gemm_mma<128, 64>,
                         cudaFuncAttributeMaxDynamicSharedMemorySize, DS2);

    // ---- prep ----
    k_prep_zero<<<gN, 256>>>();
    k_count<<<gE, 256>>>(src, dst, eid);
    k_scan<<<1, 1>>>();
    k_scatter<<<gE, 256>>>(eid);
    k_scan_blk<<<SCAN_NB, SCAN_BS>>>();
    k_scan_top<<<1, 32>>>();
    k_scan_add<<<gN, 256>>>();
    k_dscatter<<<gE, 256>>>(dst);
    k_round_all<<<(RTOT + 255) / 256, 256>>>(W1, W2, edge_feat, node_emb);
    k_zn<<<(N_ + 3) / 4, 128>>>(node_emb, A1, A2);

    // ---- layer 1: FIN=64, K=192, NOUT=128 ----
    k_gemm_mma<64, 128><<<MT, 256, DS1>>>(d_Wt1, A1 + EMB_, d_zn1, src, dst);
    k_aggfinal<128, true><<<(N_ + 31) / 32, 256>>>(node_emb, L1, b1, nullptr);

    // ---- layer 2: FIN=128, K=256, NOUT=64 ----
    k_gemm_mma<128, 64><<<MT, 256, DS2>>>(d_Wt2, A2 + EMB_, d_zn2, src, dst);
    k_aggfinal<64, false><<<(N_ + 31) / 32, 256>>>(node_emb, L2, b2, out);
}